// round 1
// baseline (speedup 1.0000x reference)
#include <cuda_runtime.h>
#include <math.h>

#define HID 128
#define G 32
#define DEPTH 4
#define N_MAX 30720
#define E_MAX 524288

// ---------------- scratch ----------------
__device__ float g_h0[N_MAX * HID];
__device__ float g_h1[N_MAX * HID];
__device__ float g_xp[N_MAX * HID];
__device__ float g_asn[N_MAX * 4];
__device__ float g_adn[N_MAX * 4];
__device__ int   g_cnt[N_MAX];
__device__ int   g_cur[N_MAX];
__device__ int   g_indptr[N_MAX + 1];
__device__ int   g_csr[E_MAX];
__device__ float g_temb[HID];
__device__ float g_pool[2 * G * HID];
__device__ int   g_gcnt[2 * G];
__device__ float g_m1[G * 256];
__device__ float g_m2[G * HID];

// ---------------- time embedding (t = 0 for all groups) ----------------
// te = [zeros(16), ones(16)]; temb = silu(te @ w1^T + b1) @ w2^T + b2  (one 128-vec)
__global__ void k_temb(const float* __restrict__ w1, const float* __restrict__ b1,
                       const float* __restrict__ w2, const float* __restrict__ b2,
                       float* __restrict__ temb) {
    __shared__ float u[128];
    int j = threadIdx.x;
    float s = b1[j];
    #pragma unroll
    for (int k = 16; k < 32; k++) s += w1[j * 32 + k];
    u[j] = s / (1.f + expf(-s));
    __syncthreads();
    float o = b2[j];
    #pragma unroll 8
    for (int i = 0; i < 128; i++) o += u[i] * w2[j * 128 + i];
    temb[j] = o;
}

// ---------------- CSR build ----------------
__global__ void k_initcnt(int* cnt, int* cur, int N) {
    int i = blockIdx.x * blockDim.x + threadIdx.x;
    if (i < N) { cnt[i] = 1; cur[i] = 1; }  // self-loop reserved at slot 0
}
__global__ void k_count(const int* __restrict__ dst, int* cnt, int E) {
    int i = blockIdx.x * blockDim.x + threadIdx.x;
    if (i < E) atomicAdd(&cnt[dst[i]], 1);
}
__global__ void k_scan(const int* __restrict__ cnt, int* __restrict__ indptr, int N) {
    __shared__ int part[1024];
    int t = threadIdx.x;
    int ch = (N + 1023) >> 10;
    int beg = t * ch;
    int s = 0;
    for (int i = 0; i < ch; i++) { int idx = beg + i; if (idx < N) s += cnt[idx]; }
    part[t] = s;
    __syncthreads();
    for (int off = 1; off < 1024; off <<= 1) {
        int v = (t >= off) ? part[t - off] : 0;
        __syncthreads();
        part[t] += v;
        __syncthreads();
    }
    int run = (t == 0) ? 0 : part[t - 1];
    for (int i = 0; i < ch; i++) {
        int idx = beg + i;
        if (idx < N) { indptr[idx] = run; run += cnt[idx]; }
    }
    if (t == 0) indptr[N] = part[1023];
}
__global__ void k_self(const int* __restrict__ indptr, int* __restrict__ csr, int N) {
    int i = blockIdx.x * blockDim.x + threadIdx.x;
    if (i < N) csr[indptr[i]] = i;
}
__global__ void k_fill(const int* __restrict__ srcs, const int* __restrict__ dsts,
                       const int* __restrict__ indptr, int* cur, int* __restrict__ csr, int E) {
    int i = blockIdx.x * blockDim.x + threadIdx.x;
    if (i < E) {
        int d = dsts[i];
        int p = indptr[d] + atomicAdd(&cur[d], 1);
        csr[p] = srcs[i];
    }
}

// ---------------- encoder: h = x @ ew^T + eb + temb ----------------
__global__ void k_encode(const float* __restrict__ x, const float* __restrict__ ew,
                         const float* __restrict__ eb, const float* __restrict__ temb,
                         float* __restrict__ h, int N) {
    __shared__ float sw[128 * 16];
    __shared__ float sb[128];
    __shared__ float sx[32 * 16];
    int t = threadIdx.x;
    for (int i = t; i < 2048; i += 256) sw[i] = ew[i];
    if (t < 128) sb[t] = eb[t] + temb[t];
    int n0 = blockIdx.x * 32;
    for (int i = t; i < 512; i += 256) {
        int n = n0 + (i >> 4);
        sx[i] = (n < N) ? x[n * 16 + (i & 15)] : 0.f;
    }
    __syncthreads();
    for (int idx = t; idx < 32 * 128; idx += 256) {
        int m = idx >> 7, j = idx & 127;
        int n = n0 + m;
        if (n >= N) continue;
        float s = sb[j];
        #pragma unroll
        for (int k = 0; k < 16; k++) s += sx[m * 16 + k] * sw[j * 16 + k];
        h[n * 128 + j] = s;
    }
}

// ---------------- GEMM: xp = h @ W^T, tile 32 rows x 128 cols ----------------
__global__ void k_gemm(const float* __restrict__ h, const float* __restrict__ W,
                       float* __restrict__ xp, int N) {
    __shared__ float sW[32][132];  // [k][j]
    __shared__ float sH[32][36];   // [k][m]
    int t = threadIdx.x;
    int n0 = blockIdx.x * 32;
    int tm = (t >> 5) << 2;   // 0..28
    int tj = (t & 31) << 2;   // 0..124
    float acc[4][4] = {};
    for (int kk = 0; kk < 128; kk += 32) {
        for (int i = t; i < 4096; i += 256) {
            int j = i >> 5, k = i & 31;
            sW[k][j] = W[j * 128 + kk + k];
        }
        for (int i = t; i < 1024; i += 256) {
            int m = i >> 5, k = i & 31;
            int n = n0 + m;
            sH[k][m] = (n < N) ? h[n * 128 + kk + k] : 0.f;
        }
        __syncthreads();
        #pragma unroll
        for (int k = 0; k < 32; k++) {
            float4 bv = *(const float4*)&sW[k][tj];
            float4 av = *(const float4*)&sH[k][tm];
            float a[4] = {av.x, av.y, av.z, av.w};
            float b[4] = {bv.x, bv.y, bv.z, bv.w};
            #pragma unroll
            for (int mi = 0; mi < 4; mi++)
                #pragma unroll
                for (int ji = 0; ji < 4; ji++)
                    acc[mi][ji] += a[mi] * b[ji];
        }
        __syncthreads();
    }
    #pragma unroll
    for (int mi = 0; mi < 4; mi++) {
        int n = n0 + tm + mi;
        if (n < N) {
            float4 o = make_float4(acc[mi][0], acc[mi][1], acc[mi][2], acc[mi][3]);
            *(float4*)&xp[n * 128 + tj] = o;
        }
    }
}

// ---------------- attention coefficients: asn/adn [N,4] ----------------
__global__ void k_attn(const float* __restrict__ xp, const float* __restrict__ a_s,
                       const float* __restrict__ a_d, float* __restrict__ asn,
                       float* __restrict__ adn, int N) {
    int warp = (blockIdx.x * blockDim.x + threadIdx.x) >> 5;
    int lane = threadIdx.x & 31;
    if (warp >= N) return;
    int hd = lane >> 3;
    int j = lane * 4;  // == hd*32 + (lane&7)*4
    float4 xv = *(const float4*)&xp[warp * 128 + j];
    float4 av = *(const float4*)&a_s[j];
    float4 dv = *(const float4*)&a_d[j];
    float ps = xv.x * av.x + xv.y * av.y + xv.z * av.z + xv.w * av.w;
    float pd = xv.x * dv.x + xv.y * dv.y + xv.z * dv.z + xv.w * dv.w;
    #pragma unroll
    for (int off = 4; off >= 1; off >>= 1) {
        ps += __shfl_down_sync(0xffffffff, ps, off);
        pd += __shfl_down_sync(0xffffffff, pd, off);
    }
    if ((lane & 7) == 0) { asn[warp * 4 + hd] = ps; adn[warp * 4 + hd] = pd; }
}

// ---------------- aggregation: warp-per-node online softmax over CSR ----------------
__global__ void k_aggr(const float* __restrict__ xp, const float* __restrict__ asn,
                       const float* __restrict__ adn, const float* __restrict__ bias,
                       const int* __restrict__ indptr, const int* __restrict__ csr,
                       float* __restrict__ hout, int N) {
    int warp = (blockIdx.x * blockDim.x + threadIdx.x) >> 5;
    int lane = threadIdx.x & 31;
    if (warp >= N) return;
    int n = warp;
    int hd = lane >> 3;
    int j = lane * 4;
    int base = indptr[n], end = indptr[n + 1];
    float adn_n = adn[n * 4 + hd];
    float mymax = -1e30f, denom = 0.f;
    float4 acc = make_float4(0.f, 0.f, 0.f, 0.f);
    int src = csr[base];
    float4 xv = *(const float4*)&xp[src * 128 + j];
    float av = asn[src * 4 + hd];
    for (int i = base; i < end; i++) {
        float4 nxv; float nav;
        if (i + 1 < end) {
            int nsrc = csr[i + 1];
            nxv = *(const float4*)&xp[nsrc * 128 + j];
            nav = asn[nsrc * 4 + hd];
        }
        float e = av + adn_n;
        e = (e >= 0.f) ? e : 0.2f * e;                 // leaky_relu 0.2
        float nm = fmaxf(mymax, e);
        float corr = __expf(mymax - nm);               // 0 on first edge
        float w = __expf(e - nm);
        denom = denom * corr + w;
        acc.x = acc.x * corr + w * xv.x;
        acc.y = acc.y * corr + w * xv.y;
        acc.z = acc.z * corr + w * xv.z;
        acc.w = acc.w * corr + w * xv.w;
        mymax = nm;
        xv = nxv; av = nav;
    }
    float inv = 1.f / (denom + 1e-16f);
    float4 o;
    o.x = fmaxf(acc.x * inv + bias[j + 0], 0.f);
    o.y = fmaxf(acc.y * inv + bias[j + 1], 0.f);
    o.z = fmaxf(acc.z * inv + bias[j + 2], 0.f);
    o.w = fmaxf(acc.w * inv + bias[j + 3], 0.f);
    *(float4*)&hout[n * 128 + j] = o;
}

// ---------------- pooling ----------------
__global__ void k_zero(float* pool, int* gc) {
    int i = blockIdx.x * blockDim.x + threadIdx.x;
    if (i < 2 * G * HID) pool[i] = 0.f;
    if (i < 2 * G) gc[i] = 0;
}
__global__ void k_pool(const float* __restrict__ h, const int* __restrict__ batch,
                       float* pool, int N) {
    int j = threadIdx.x;  // 128
    int n0 = blockIdx.x * 64;
    if (n0 >= N) return;
    int nend = min(n0 + 64, N);
    int curg = batch[n0];
    float acc = 0.f;
    for (int n = n0; n < nend; n++) {
        int g = batch[n];
        if (g != curg) {
            atomicAdd(&pool[curg * HID + j], acc);
            acc = 0.f; curg = g;
        }
        acc += h[n * HID + j];
    }
    atomicAdd(&pool[curg * HID + j], acc);
}
__global__ void k_gcnt(const int* __restrict__ batch, int* gc, int N) {
    int i = blockIdx.x * blockDim.x + threadIdx.x;
    if (i < N) atomicAdd(&gc[batch[i]], 1);
}

// ---------------- prediction MLP ----------------
__global__ void k_mlp1(const float* __restrict__ pool, const int* __restrict__ gc,
                       const float* __restrict__ w, const float* __restrict__ b,
                       float* __restrict__ out) {
    int g = blockIdx.x, o = threadIdx.x;  // 256 threads
    __shared__ float jv[256];
    if (o < 128) {
        float c = fmaxf((float)gc[g], 1.f);
        jv[o] = pool[g * HID + o] / c;
    } else {
        float c = fmaxf((float)gc[G + g], 1.f);
        jv[o] = pool[G * HID + g * HID + (o - 128)] / c;
    }
    __syncthreads();
    float s = b[o];
    #pragma unroll 8
    for (int c2 = 0; c2 < 256; c2++) s += jv[c2] * w[o * 256 + c2];
    out[g * 256 + o] = fmaxf(s, 0.f);
}
__global__ void k_mlp2(const float* __restrict__ in, const float* __restrict__ w,
                       const float* __restrict__ b, float* __restrict__ out) {
    int g = blockIdx.x, o = threadIdx.x;  // 128 threads
    __shared__ float jv[256];
    jv[o] = in[g * 256 + o];
    jv[o + 128] = in[g * 256 + o + 128];
    __syncthreads();
    float s = b[o];
    #pragma unroll 8
    for (int c2 = 0; c2 < 256; c2++) s += jv[c2] * w[o * 256 + c2];
    out[g * 128 + o] = fmaxf(s, 0.f);
}
__global__ void k_mlp3(const float* __restrict__ in, const float* __restrict__ w,
                       const float* __restrict__ b, float* __restrict__ out) {
    int g = threadIdx.x;
    if (g < G) {
        float s = b[0];
        #pragma unroll 8
        for (int c = 0; c < 128; c++) s += in[g * 128 + c] * w[c];
        out[g] = s;
    }
}

// ---------------- launch ----------------
extern "C" void kernel_launch(void* const* d_in, const int* in_sizes, int n_in,
                              void* d_out, int out_size) {
    const float* px  = (const float*)d_in[0];
    const int*   pei = (const int*)d_in[1];
    const int*   pb  = (const int*)d_in[2];
    const float* lx  = (const float*)d_in[3];
    const int*   lei = (const int*)d_in[4];
    const int*   lb  = (const int*)d_in[5];
    const float* tw1 = (const float*)d_in[6];
    const float* tb1 = (const float*)d_in[7];
    const float* tw2 = (const float*)d_in[8];
    const float* tb2 = (const float*)d_in[9];
    const float* pew = (const float*)d_in[10];
    const float* peb = (const float*)d_in[11];
    const float* lew = (const float*)d_in[12];
    const float* leb = (const float*)d_in[13];
    const float* pgW = (const float*)d_in[14];
    const float* pgs = (const float*)d_in[15];
    const float* pgd = (const float*)d_in[16];
    const float* pgb = (const float*)d_in[17];
    const float* lgW = (const float*)d_in[18];
    const float* lgs = (const float*)d_in[19];
    const float* lgd = (const float*)d_in[20];
    const float* lgb = (const float*)d_in[21];
    const float* prw1 = (const float*)d_in[22];
    const float* prb1 = (const float*)d_in[23];
    const float* prw2 = (const float*)d_in[24];
    const float* prb2 = (const float*)d_in[25];
    const float* prw3 = (const float*)d_in[26];
    const float* prb3 = (const float*)d_in[27];

    int Np = in_sizes[0] / 16, Ep = in_sizes[1] / 2;
    int Nl = in_sizes[3] / 16, El = in_sizes[4] / 2;

    float *h0, *h1, *xp, *asn, *adn, *temb, *pool, *m1, *m2;
    int *cnt, *cur, *indptr, *csr, *gc;
    cudaGetSymbolAddress((void**)&h0, g_h0);
    cudaGetSymbolAddress((void**)&h1, g_h1);
    cudaGetSymbolAddress((void**)&xp, g_xp);
    cudaGetSymbolAddress((void**)&asn, g_asn);
    cudaGetSymbolAddress((void**)&adn, g_adn);
    cudaGetSymbolAddress((void**)&temb, g_temb);
    cudaGetSymbolAddress((void**)&pool, g_pool);
    cudaGetSymbolAddress((void**)&m1, g_m1);
    cudaGetSymbolAddress((void**)&m2, g_m2);
    cudaGetSymbolAddress((void**)&cnt, g_cnt);
    cudaGetSymbolAddress((void**)&cur, g_cur);
    cudaGetSymbolAddress((void**)&indptr, g_indptr);
    cudaGetSymbolAddress((void**)&csr, g_csr);
    cudaGetSymbolAddress((void**)&gc, g_gcnt);

    k_temb<<<1, 128>>>(tw1, tb1, tw2, tb2, temb);
    k_zero<<<32, 256>>>(pool, gc);

    for (int br = 0; br < 2; br++) {
        const float* x   = br ? lx  : px;
        const int*   ei  = br ? lei : pei;
        const int*   bat = br ? lb  : pb;
        int N = br ? Nl : Np;
        int E = br ? El : Ep;
        const float* ew = br ? lew : pew;
        const float* eb = br ? leb : peb;
        const float* W  = br ? lgW : pgW;
        const float* As = br ? lgs : pgs;
        const float* Ad = br ? lgd : pgd;
        const float* Bs = br ? lgb : pgb;

        int nb256 = (N + 255) / 256;
        int eb256 = (E + 255) / 256;
        k_initcnt<<<nb256, 256>>>(cnt, cur, N);
        k_count<<<eb256, 256>>>(ei + E, cnt, E);
        k_scan<<<1, 1024>>>(cnt, indptr, N);
        k_self<<<nb256, 256>>>(indptr, csr, N);
        k_fill<<<eb256, 256>>>(ei, ei + E, indptr, cur, csr, E);

        k_encode<<<(N + 31) / 32, 256>>>(x, ew, eb, temb, h0, N);

        float* hin = h0;
        float* hout = h1;
        int warpsblk = (N * 32 + 255) / 256;
        for (int l = 0; l < DEPTH; l++) {
            k_gemm<<<(N + 31) / 32, 256>>>(hin, W + l * HID * HID, xp, N);
            k_attn<<<warpsblk, 256>>>(xp, As + l * HID, Ad + l * HID, asn, adn, N);
            k_aggr<<<warpsblk, 256>>>(xp, asn, adn, Bs + l * HID, indptr, csr, hout, N);
            float* tmp = hin; hin = hout; hout = tmp;
        }

        k_pool<<<(N + 63) / 64, 128>>>(hin, bat, pool + br * G * HID, N);
        k_gcnt<<<nb256, 256>>>(bat, gc + br * G, N);
    }

    k_mlp1<<<G, 256>>>(pool, gc, prw1, prb1, m1);
    k_mlp2<<<G, 128>>>(m1, prw2, prb2, m2);
    k_mlp3<<<1, 32>>>(m2, prw3, prb3, (float*)d_out);
}

// round 2
// speedup vs baseline: 1.2135x; 1.2135x over previous
#include <cuda_runtime.h>
#include <math.h>

#define HID 128
#define G 32
#define DEPTH 4
#define N_MAX 46080
#define E_MAX 640000

// ---------------- scratch ----------------
__device__ float g_h0[N_MAX * HID];
__device__ float g_h1[N_MAX * HID];
__device__ float g_xp[N_MAX * HID];
__device__ float g_asn[N_MAX * 4];
__device__ float g_adn[N_MAX * 4];
__device__ int   g_cnt[N_MAX];
__device__ int   g_cur[N_MAX];
__device__ int   g_indptr[N_MAX + 1];
__device__ int   g_csr[E_MAX];
__device__ float g_temb[HID];
__device__ float g_pool[2 * G * HID];
__device__ int   g_gcnt[2 * G];
__device__ float g_m1[G * 256];
__device__ float g_m2[G * HID];

// ---------------- setup: temb (block 0) + cnt/cur/pool/gcnt init (blocks >=1) ----------------
// te = [zeros(16), ones(16)]; temb = silu(te @ w1^T + b1) @ w2^T + b2
__global__ void k_setup(const float* __restrict__ w1, const float* __restrict__ b1,
                        const float* __restrict__ w2, const float* __restrict__ b2,
                        float* __restrict__ temb,
                        int* __restrict__ cnt, int* __restrict__ cur,
                        float* __restrict__ pool, int* __restrict__ gc,
                        int Np, int NpPad, int Nl, int NT) {
    int t = threadIdx.x;
    if (blockIdx.x == 0) {
        __shared__ float u[128];
        if (t < 128) {
            float s = b1[t];
            #pragma unroll
            for (int k = 16; k < 32; k++) s += w1[t * 32 + k];
            u[t] = s / (1.f + expf(-s));
        }
        __syncthreads();
        if (t < 128) {
            float o = b2[t];
            #pragma unroll 8
            for (int i = 0; i < 128; i++) o += u[i] * w2[t * 128 + i];
            temb[t] = o;
        }
        return;
    }
    int i = (blockIdx.x - 1) * 256 + t;
    if (i < NT) {
        bool valid = (i < Np) || (i >= NpPad && (i - NpPad) < Nl);
        cnt[i] = valid ? 1 : 0;   // slot 0 reserved for self-loop
        cur[i] = valid ? 1 : 0;
    }
    if (i < 2 * G * HID) pool[i] = 0.f;
    if (i < 2 * G) gc[i] = 0;
}

// ---------------- CSR: count (both edge lists) ----------------
__global__ void k_count(const int* __restrict__ pdst, const int* __restrict__ ldst,
                        int* cnt, int Ep, int El, int NpPad) {
    int i = blockIdx.x * blockDim.x + threadIdx.x;
    if (i < Ep) atomicAdd(&cnt[pdst[i]], 1);
    else if (i < Ep + El) atomicAdd(&cnt[ldst[i - Ep] + NpPad], 1);
}

__global__ void k_scan(const int* __restrict__ cnt, int* __restrict__ indptr, int N) {
    __shared__ int part[1024];
    int t = threadIdx.x;
    int ch = (N + 1023) >> 10;
    int beg = t * ch;
    int s = 0;
    for (int i = 0; i < ch; i++) { int idx = beg + i; if (idx < N) s += cnt[idx]; }
    part[t] = s;
    __syncthreads();
    for (int off = 1; off < 1024; off <<= 1) {
        int v = (t >= off) ? part[t - off] : 0;
        __syncthreads();
        part[t] += v;
        __syncthreads();
    }
    int run = (t == 0) ? 0 : part[t - 1];
    for (int i = 0; i < ch; i++) {
        int idx = beg + i;
        if (idx < N) { indptr[idx] = run; run += cnt[idx]; }
    }
    if (t == 0) indptr[N] = part[1023];
}

// ---------------- CSR: self-loops + edge fill, one launch ----------------
__global__ void k_selffill(const int* __restrict__ psrc, const int* __restrict__ pdst,
                           const int* __restrict__ lsrc, const int* __restrict__ ldst,
                           const int* __restrict__ indptr, int* cur, int* __restrict__ csr,
                           int Ep, int El, int Np, int NpPad, int Nl, int NT) {
    int i = blockIdx.x * blockDim.x + threadIdx.x;
    if (i < NT) {
        bool valid = (i < Np) || (i >= NpPad && (i - NpPad) < Nl);
        if (valid) csr[indptr[i]] = i;
    }
    if (i < Ep) {
        int d = pdst[i];
        int p = indptr[d] + atomicAdd(&cur[d], 1);
        csr[p] = psrc[i];
    } else if (i < Ep + El) {
        int e = i - Ep;
        int d = ldst[e] + NpPad;
        int p = indptr[d] + atomicAdd(&cur[d], 1);
        csr[p] = lsrc[e] + NpPad;
    }
}

// ---------------- encoder (both regions): h = x @ ew^T + eb + temb ----------------
__global__ void k_encode(const float* __restrict__ px, const float* __restrict__ lx,
                         const float* __restrict__ pew, const float* __restrict__ peb,
                         const float* __restrict__ lew, const float* __restrict__ leb,
                         const float* __restrict__ temb, float* __restrict__ h,
                         int Np, int NpPad, int Nl, int nbP) {
    __shared__ float sw[128 * 16];
    __shared__ float sb[128];
    __shared__ float sx[32 * 16];
    int t = threadIdx.x;
    int blk = blockIdx.x;
    const float* x; const float* ew; const float* ebp;
    int n0, Nv, base;
    if (blk < nbP) { x = px; ew = pew; ebp = peb; n0 = blk * 32; Nv = Np; base = 0; }
    else { x = lx; ew = lew; ebp = leb; n0 = NpPad + (blk - nbP) * 32; Nv = Nl; base = NpPad; }
    for (int i = t; i < 2048; i += 256) sw[i] = ew[i];
    if (t < 128) sb[t] = ebp[t] + temb[t];
    for (int i = t; i < 512; i += 256) {
        int m = i >> 4;
        int loc = n0 - base + m;
        sx[i] = (loc < Nv) ? x[loc * 16 + (i & 15)] : 0.f;
    }
    __syncthreads();
    for (int idx = t; idx < 32 * 128; idx += 256) {
        int m = idx >> 7, j = idx & 127;
        if (n0 - base + m >= Nv) continue;
        float s = sb[j];
        #pragma unroll
        for (int k = 0; k < 16; k++) s += sx[m * 16 + k] * sw[j * 16 + k];
        h[(n0 + m) * 128 + j] = s;
    }
}

// ---------------- GEMM 64x128 tile + fused attention coefficients ----------------
__global__ void __launch_bounds__(256) k_gemm_attn(
        const float* __restrict__ h,
        const float* __restrict__ Wp, const float* __restrict__ Wl,
        const float* __restrict__ asp, const float* __restrict__ adp,
        const float* __restrict__ asl, const float* __restrict__ adl,
        float* __restrict__ xp, float* __restrict__ asn, float* __restrict__ adn,
        int Np, int NpPad, int Nl, int nbP) {
    __shared__ float sW[32][132];  // [k][j]
    __shared__ float sH[32][72];   // [k][m]
    int t = threadIdx.x;
    int blk = blockIdx.x;
    const float* W; const float* As; const float* Ad;
    int n0, Nv, base;
    if (blk < nbP) { W = Wp; As = asp; Ad = adp; n0 = blk * 64; Nv = Np; base = 0; }
    else { W = Wl; As = asl; Ad = adl; n0 = NpPad + (blk - nbP) * 64; Nv = Nl; base = NpPad; }

    int lane = t & 31;
    int tm = (t >> 5) * 8;    // row group of this warp (8 rows)
    int tj = lane * 4;        // 4 cols of this lane
    float acc[8][4] = {};

    for (int kk = 0; kk < 128; kk += 32) {
        // load W tile: 128x32 as float4 along k
        for (int i = t; i < 1024; i += 256) {
            int j = i >> 3, kq = (i & 7) * 4;
            float4 wv = *(const float4*)&W[j * 128 + kk + kq];
            sW[kq + 0][j] = wv.x; sW[kq + 1][j] = wv.y;
            sW[kq + 2][j] = wv.z; sW[kq + 3][j] = wv.w;
        }
        // load H tile: 64x32
        for (int i = t; i < 512; i += 256) {
            int m = i >> 3, kq = (i & 7) * 4;
            float4 hv = make_float4(0.f, 0.f, 0.f, 0.f);
            if (n0 - base + m < Nv) hv = *(const float4*)&h[(n0 + m) * 128 + kk + kq];
            sH[kq + 0][m] = hv.x; sH[kq + 1][m] = hv.y;
            sH[kq + 2][m] = hv.z; sH[kq + 3][m] = hv.w;
        }
        __syncthreads();
        #pragma unroll
        for (int k = 0; k < 32; k++) {
            float4 bv = *(const float4*)&sW[k][tj];
            float4 a0 = *(const float4*)&sH[k][tm];
            float4 a1 = *(const float4*)&sH[k][tm + 4];
            float a[8] = {a0.x, a0.y, a0.z, a0.w, a1.x, a1.y, a1.z, a1.w};
            float b[4] = {bv.x, bv.y, bv.z, bv.w};
            #pragma unroll
            for (int mi = 0; mi < 8; mi++)
                #pragma unroll
                for (int ji = 0; ji < 4; ji++)
                    acc[mi][ji] += a[mi] * b[ji];
        }
        __syncthreads();
    }

    // epilogue: store xp + fused attention coefficients
    float4 as4 = *(const float4*)&As[tj];
    float4 ad4 = *(const float4*)&Ad[tj];
    int hd = lane >> 3;
    #pragma unroll
    for (int mi = 0; mi < 8; mi++) {
        int n = n0 + tm + mi;
        bool valid = (n - base) < Nv;
        if (valid) {
            float4 o = make_float4(acc[mi][0], acc[mi][1], acc[mi][2], acc[mi][3]);
            *(float4*)&xp[n * 128 + tj] = o;
        }
        float ps = acc[mi][0] * as4.x + acc[mi][1] * as4.y + acc[mi][2] * as4.z + acc[mi][3] * as4.w;
        float pd = acc[mi][0] * ad4.x + acc[mi][1] * ad4.y + acc[mi][2] * ad4.z + acc[mi][3] * ad4.w;
        #pragma unroll
        for (int off = 4; off >= 1; off >>= 1) {
            ps += __shfl_down_sync(0xffffffff, ps, off);
            pd += __shfl_down_sync(0xffffffff, pd, off);
        }
        if ((lane & 7) == 0 && valid) {
            asn[n * 4 + hd] = ps;
            adn[n * 4 + hd] = pd;
        }
    }
}

// ---------------- aggregation: warp-per-node online softmax over CSR ----------------
__global__ void k_aggr(const float* __restrict__ xp, const float* __restrict__ asn,
                       const float* __restrict__ adn,
                       const float* __restrict__ biasP, const float* __restrict__ biasL,
                       const int* __restrict__ indptr, const int* __restrict__ csr,
                       float* __restrict__ hout, int Np, int NpPad, int Nl) {
    int n = (blockIdx.x * blockDim.x + threadIdx.x) >> 5;
    int lane = threadIdx.x & 31;
    const float* bias;
    if (n < NpPad) { if (n >= Np) return; bias = biasP; }
    else { if (n - NpPad >= Nl) return; bias = biasL; }
    int hd = lane >> 3;
    int j = lane * 4;
    int base = indptr[n], end = indptr[n + 1];
    float adn_n = adn[n * 4 + hd];
    float mymax = -1e30f, denom = 0.f;
    float4 acc = make_float4(0.f, 0.f, 0.f, 0.f);
    int src = csr[base];
    float4 xv = *(const float4*)&xp[src * 128 + j];
    float av = asn[src * 4 + hd];
    for (int i = base; i < end; i++) {
        float4 nxv; float nav;
        if (i + 1 < end) {
            int nsrc = csr[i + 1];
            nxv = *(const float4*)&xp[nsrc * 128 + j];
            nav = asn[nsrc * 4 + hd];
        }
        float e = av + adn_n;
        e = (e >= 0.f) ? e : 0.2f * e;                 // leaky_relu 0.2
        float nm = fmaxf(mymax, e);
        float corr = __expf(mymax - nm);               // 0 on first edge
        float w = __expf(e - nm);
        denom = denom * corr + w;
        acc.x = acc.x * corr + w * xv.x;
        acc.y = acc.y * corr + w * xv.y;
        acc.z = acc.z * corr + w * xv.z;
        acc.w = acc.w * corr + w * xv.w;
        mymax = nm;
        xv = nxv; av = nav;
    }
    float inv = 1.f / (denom + 1e-16f);
    float4 o;
    o.x = fmaxf(acc.x * inv + bias[j + 0], 0.f);
    o.y = fmaxf(acc.y * inv + bias[j + 1], 0.f);
    o.z = fmaxf(acc.z * inv + bias[j + 2], 0.f);
    o.w = fmaxf(acc.w * inv + bias[j + 3], 0.f);
    *(float4*)&hout[n * 128 + j] = o;
}

// ---------------- pooling (sum + counts, both regions) ----------------
__global__ void k_pool(const float* __restrict__ h, const int* __restrict__ pb,
                       const int* __restrict__ lb, float* pool, int* gc,
                       int Np, int NpPad, int Nl) {
    int j = threadIdx.x;  // 128
    int n0 = blockIdx.x * 64;
    int nend = n0 + 64;
    int curg = -1;
    float acc = 0.f;
    int cacc = 0;
    for (int n = n0; n < nend; n++) {
        int g;
        if (n < Np) g = pb[n];
        else if (n >= NpPad && (n - NpPad) < Nl) g = G + lb[n - NpPad];
        else continue;
        if (g != curg) {
            if (curg >= 0) {
                atomicAdd(&pool[curg * HID + j], acc);
                if (j == 0) atomicAdd(&gc[curg], cacc);
            }
            curg = g; acc = 0.f; cacc = 0;
        }
        acc += h[n * HID + j];
        cacc++;
    }
    if (curg >= 0) {
        atomicAdd(&pool[curg * HID + j], acc);
        if (j == 0) atomicAdd(&gc[curg], cacc);
    }
}

// ---------------- prediction MLP ----------------
__global__ void k_mlp1(const float* __restrict__ pool, const int* __restrict__ gc,
                       const float* __restrict__ w, const float* __restrict__ b,
                       float* __restrict__ out) {
    int g = blockIdx.x, o = threadIdx.x;  // 256 threads
    __shared__ float jv[256];
    if (o < 128) {
        float c = fmaxf((float)gc[g], 1.f);
        jv[o] = pool[g * HID + o] / c;
    } else {
        float c = fmaxf((float)gc[G + g], 1.f);
        jv[o] = pool[(G + g) * HID + (o - 128)] / c;
    }
    __syncthreads();
    float s = b[o];
    #pragma unroll 8
    for (int c2 = 0; c2 < 256; c2++) s += jv[c2] * w[o * 256 + c2];
    out[g * 256 + o] = fmaxf(s, 0.f);
}
__global__ void k_mlp2(const float* __restrict__ in, const float* __restrict__ w,
                       const float* __restrict__ b, float* __restrict__ out) {
    int g = blockIdx.x, o = threadIdx.x;  // 128 threads
    __shared__ float jv[256];
    jv[o] = in[g * 256 + o];
    jv[o + 128] = in[g * 256 + o + 128];
    __syncthreads();
    float s = b[o];
    #pragma unroll 8
    for (int c2 = 0; c2 < 256; c2++) s += jv[c2] * w[o * 256 + c2];
    out[g * 128 + o] = fmaxf(s, 0.f);
}
__global__ void k_mlp3(const float* __restrict__ in, const float* __restrict__ w,
                       const float* __restrict__ b, float* __restrict__ out) {
    int g = threadIdx.x;
    if (g < G) {
        float s = b[0];
        #pragma unroll 8
        for (int c = 0; c < 128; c++) s += in[g * 128 + c] * w[c];
        out[g] = s;
    }
}

// ---------------- launch ----------------
extern "C" void kernel_launch(void* const* d_in, const int* in_sizes, int n_in,
                              void* d_out, int out_size) {
    const float* px  = (const float*)d_in[0];
    const int*   pei = (const int*)d_in[1];
    const int*   pb  = (const int*)d_in[2];
    const float* lx  = (const float*)d_in[3];
    const int*   lei = (const int*)d_in[4];
    const int*   lb  = (const int*)d_in[5];
    const float* tw1 = (const float*)d_in[6];
    const float* tb1 = (const float*)d_in[7];
    const float* tw2 = (const float*)d_in[8];
    const float* tb2 = (const float*)d_in[9];
    const float* pew = (const float*)d_in[10];
    const float* peb = (const float*)d_in[11];
    const float* lew = (const float*)d_in[12];
    const float* leb = (const float*)d_in[13];
    const float* pgW = (const float*)d_in[14];
    const float* pgs = (const float*)d_in[15];
    const float* pgd = (const float*)d_in[16];
    const float* pgb = (const float*)d_in[17];
    const float* lgW = (const float*)d_in[18];
    const float* lgs = (const float*)d_in[19];
    const float* lgd = (const float*)d_in[20];
    const float* lgb = (const float*)d_in[21];
    const float* prw1 = (const float*)d_in[22];
    const float* prb1 = (const float*)d_in[23];
    const float* prw2 = (const float*)d_in[24];
    const float* prb2 = (const float*)d_in[25];
    const float* prw3 = (const float*)d_in[26];
    const float* prb3 = (const float*)d_in[27];

    int Np = in_sizes[0] / 16, Ep = in_sizes[1] / 2;
    int Nl = in_sizes[3] / 16, El = in_sizes[4] / 2;
    int NpPad = (Np + 63) / 64 * 64;
    int NT = NpPad + (Nl + 63) / 64 * 64;   // padded total node space
    int Etot = Ep + El;

    float *h0, *h1, *xp, *asn, *adn, *temb, *pool, *m1, *m2;
    int *cnt, *cur, *indptr, *csr, *gc;
    cudaGetSymbolAddress((void**)&h0, g_h0);
    cudaGetSymbolAddress((void**)&h1, g_h1);
    cudaGetSymbolAddress((void**)&xp, g_xp);
    cudaGetSymbolAddress((void**)&asn, g_asn);
    cudaGetSymbolAddress((void**)&adn, g_adn);
    cudaGetSymbolAddress((void**)&temb, g_temb);
    cudaGetSymbolAddress((void**)&pool, g_pool);
    cudaGetSymbolAddress((void**)&m1, g_m1);
    cudaGetSymbolAddress((void**)&m2, g_m2);
    cudaGetSymbolAddress((void**)&cnt, g_cnt);
    cudaGetSymbolAddress((void**)&cur, g_cur);
    cudaGetSymbolAddress((void**)&indptr, g_indptr);
    cudaGetSymbolAddress((void**)&csr, g_csr);
    cudaGetSymbolAddress((void**)&gc, g_gcnt);

    const int* pdst = pei + Ep;
    const int* ldst = lei + El;

    // setup: temb + init buffers
    int setup_work = NT > 2 * G * HID ? NT : 2 * G * HID;
    k_setup<<<1 + (setup_work + 255) / 256, 256>>>(tw1, tb1, tw2, tb2, temb,
                                                   cnt, cur, pool, gc, Np, NpPad, Nl, NT);
    // CSR
    k_count<<<(Etot + 255) / 256, 256>>>(pdst, ldst, cnt, Ep, El, NpPad);
    k_scan<<<1, 1024>>>(cnt, indptr, NT);
    int sf_work = NT > Etot ? NT : Etot;
    k_selffill<<<(sf_work + 255) / 256, 256>>>(pei, pdst, lei, ldst, indptr, cur, csr,
                                               Ep, El, Np, NpPad, Nl, NT);
    // encode
    int nbP32 = NpPad / 32, nbL32 = (Nl + 31) / 32;
    k_encode<<<nbP32 + nbL32, 256>>>(px, lx, pew, peb, lew, leb, temb, h0,
                                     Np, NpPad, Nl, nbP32);

    // GAT layers
    int nbP64 = NpPad / 64, nbL64 = (Nl + 63) / 64;
    int nAggr = NpPad + Nl;
    int aggrBlocks = (nAggr * 32 + 255) / 256;
    float* hin = h0;
    float* hout = h1;
    for (int l = 0; l < DEPTH; l++) {
        k_gemm_attn<<<nbP64 + nbL64, 256>>>(hin,
            pgW + l * HID * HID, lgW + l * HID * HID,
            pgs + l * HID, pgd + l * HID, lgs + l * HID, lgd + l * HID,
            xp, asn, adn, Np, NpPad, Nl, nbP64);
        k_aggr<<<aggrBlocks, 256>>>(xp, asn, adn, pgb + l * HID, lgb + l * HID,
                                    indptr, csr, hout, Np, NpPad, Nl);
        float* tmp = hin; hin = hout; hout = tmp;
    }

    // pool + counts
    k_pool<<<(NT + 63) / 64, 128>>>(hin, pb, lb, pool, gc, Np, NpPad, Nl);

    // prediction MLP
    k_mlp1<<<G, 256>>>(pool, gc, prw1, prb1, m1);
    k_mlp2<<<G, 128>>>(m1, prw2, prb2, m2);
    k_mlp3<<<1, 32>>>(m2, prw3, prb3, (float*)d_out);
}

// round 5
// speedup vs baseline: 1.5359x; 1.2657x over previous
#include <cuda_runtime.h>
#include <math.h>

#define HID 128
#define G 32
#define DEPTH 4
#define N_MAX 46080
#define E_MAX 640000

// ---------------- scratch ----------------
__device__ float g_h0[N_MAX * HID];
__device__ float g_h1[N_MAX * HID];
__device__ float g_xp[N_MAX * HID];
__device__ float g_asn[N_MAX * 4];
__device__ float g_adn[N_MAX * 4];
__device__ int   g_cnt[N_MAX];
__device__ int   g_cur[N_MAX];
__device__ int   g_indptr[N_MAX + 1];
__device__ int   g_csr[E_MAX];
__device__ float g_temb[HID];
__device__ float g_pool[2 * G * HID];
__device__ int   g_gcnt[2 * G];
__device__ float g_m1[G * 256];
__device__ float g_m2[G * HID];

__device__ __forceinline__ unsigned to_tf32(float x) {
    unsigned r;
    asm("cvt.rna.tf32.f32 %0, %1;" : "=r"(r) : "f"(x));
    return r;
}

// ---------------- setup: temb (block 0) + cnt/cur/pool/gcnt init ----------------
__global__ void k_setup(const float* __restrict__ w1, const float* __restrict__ b1,
                        const float* __restrict__ w2, const float* __restrict__ b2,
                        float* __restrict__ temb,
                        int* __restrict__ cnt, int* __restrict__ cur,
                        float* __restrict__ pool, int* __restrict__ gc,
                        int Np, int NpPad, int Nl, int NT) {
    int t = threadIdx.x;
    if (blockIdx.x == 0) {
        __shared__ float u[128];
        if (t < 128) {
            float s = b1[t];
            #pragma unroll
            for (int k = 16; k < 32; k++) s += w1[t * 32 + k];
            u[t] = s / (1.f + expf(-s));
        }
        __syncthreads();
        if (t < 128) {
            float o = b2[t];
            #pragma unroll 8
            for (int i = 0; i < 128; i++) o += u[i] * w2[t * 128 + i];
            temb[t] = o;
        }
        return;
    }
    int i = (blockIdx.x - 1) * 256 + t;
    if (i < NT) {
        bool valid = (i < Np) || (i >= NpPad && (i - NpPad) < Nl);
        cnt[i] = valid ? 1 : 0;   // slot 0 reserved for self-loop
        cur[i] = valid ? 1 : 0;
    }
    if (i < 2 * G * HID) pool[i] = 0.f;
    if (i < 2 * G) gc[i] = 0;
}

// ---------------- CSR: count ----------------
__global__ void k_count(const int* __restrict__ pdst, const int* __restrict__ ldst,
                        int* cnt, int Ep, int El, int NpPad) {
    int i = blockIdx.x * blockDim.x + threadIdx.x;
    if (i < Ep) atomicAdd(&cnt[pdst[i]], 1);
    else if (i < Ep + El) atomicAdd(&cnt[ldst[i - Ep] + NpPad], 1);
}

__global__ void k_scan(const int* __restrict__ cnt, int* __restrict__ indptr, int N) {
    __shared__ int part[1024];
    int t = threadIdx.x;
    int ch = (N + 1023) >> 10;
    int beg = t * ch;
    int s = 0;
    for (int i = 0; i < ch; i++) { int idx = beg + i; if (idx < N) s += cnt[idx]; }
    part[t] = s;
    __syncthreads();
    for (int off = 1; off < 1024; off <<= 1) {
        int v = (t >= off) ? part[t - off] : 0;
        __syncthreads();
        part[t] += v;
        __syncthreads();
    }
    int run = (t == 0) ? 0 : part[t - 1];
    for (int i = 0; i < ch; i++) {
        int idx = beg + i;
        if (idx < N) { indptr[idx] = run; run += cnt[idx]; }
    }
    if (t == 0) indptr[N] = part[1023];
}

// ---------------- CSR: self-loops + edge fill ----------------
__global__ void k_selffill(const int* __restrict__ psrc, const int* __restrict__ pdst,
                           const int* __restrict__ lsrc, const int* __restrict__ ldst,
                           const int* __restrict__ indptr, int* cur, int* __restrict__ csr,
                           int Ep, int El, int Np, int NpPad, int Nl, int NT) {
    int i = blockIdx.x * blockDim.x + threadIdx.x;
    if (i < NT) {
        bool valid = (i < Np) || (i >= NpPad && (i - NpPad) < Nl);
        if (valid) csr[indptr[i]] = i;
    }
    if (i < Ep) {
        int d = pdst[i];
        int p = indptr[d] + atomicAdd(&cur[d], 1);
        csr[p] = psrc[i];
    } else if (i < Ep + El) {
        int e = i - Ep;
        int d = ldst[e] + NpPad;
        int p = indptr[d] + atomicAdd(&cur[d], 1);
        csr[p] = lsrc[e] + NpPad;
    }
}

// ---------------- encoder ----------------
__global__ void k_encode(const float* __restrict__ px, const float* __restrict__ lx,
                         const float* __restrict__ pew, const float* __restrict__ peb,
                         const float* __restrict__ lew, const float* __restrict__ leb,
                         const float* __restrict__ temb, float* __restrict__ h,
                         int Np, int NpPad, int Nl, int nbP) {
    __shared__ float sw[128 * 16];
    __shared__ float sb[128];
    __shared__ float sx[32 * 16];
    int t = threadIdx.x;
    int blk = blockIdx.x;
    const float* x; const float* ew; const float* ebp;
    int n0, Nv, base;
    if (blk < nbP) { x = px; ew = pew; ebp = peb; n0 = blk * 32; Nv = Np; base = 0; }
    else { x = lx; ew = lew; ebp = leb; n0 = NpPad + (blk - nbP) * 32; Nv = Nl; base = NpPad; }
    for (int i = t; i < 2048; i += 256) sw[i] = ew[i];
    if (t < 128) sb[t] = ebp[t] + temb[t];
    for (int i = t; i < 512; i += 256) {
        int m = i >> 4;
        int loc = n0 - base + m;
        sx[i] = (loc < Nv) ? x[loc * 16 + (i & 15)] : 0.f;
    }
    __syncthreads();
    for (int idx = t; idx < 32 * 128; idx += 256) {
        int m = idx >> 7, j = idx & 127;
        float s = sb[j];
        #pragma unroll
        for (int k = 0; k < 16; k++) s += sx[m * 16 + k] * sw[j * 16 + k];
        h[(n0 + m) * 128 + j] = s;   // padding rows get finite values
    }
}

// ---------------- tf32 tensor-core GEMM 64x128 + fused attention coefficients ----
// 8 warps: warp_m = wid>>1 (16 rows each), warp_n = wid&1 (64 cols each).
// Per warp: 8 accum tiles m16n8. mma.sync.m16n8k8.tf32.
__global__ void __launch_bounds__(256) k_gemm_attn(
        const float* __restrict__ h,
        const float* __restrict__ Wp, const float* __restrict__ Wl,
        const float* __restrict__ asp, const float* __restrict__ adp,
        const float* __restrict__ asl, const float* __restrict__ adl,
        float* __restrict__ xp, float* __restrict__ asn, float* __restrict__ adn,
        int NpPad, int nbP) {
    __shared__ unsigned sH[64][36];
    __shared__ unsigned sW[128][36];
    int t = threadIdx.x;
    int blk = blockIdx.x;
    const float* W; const float* As; const float* Ad;
    int n0;
    if (blk < nbP) { W = Wp; As = asp; Ad = adp; n0 = blk * 64; }
    else { W = Wl; As = asl; Ad = adl; n0 = NpPad + (blk - nbP) * 64; }

    int wid = t >> 5;
    int lane = t & 31;
    int warp_m = wid >> 1;   // 0..3
    int warp_n = wid & 1;    // 0..1
    int quad = lane >> 2;    // 0..7
    int lane4 = lane & 3;    // 0..3

    float acc[8][4];
    #pragma unroll
    for (int i = 0; i < 8; i++)
        #pragma unroll
        for (int j = 0; j < 4; j++) acc[i][j] = 0.f;

    for (int kk = 0; kk < 128; kk += 32) {
        // W tile: 128 x 32 (tf32-rounded)
        for (int i = t; i < 1024; i += 256) {
            int j = i >> 3, kq = (i & 7) * 4;
            float4 wv = *(const float4*)&W[j * 128 + kk + kq];
            uint4 cv = make_uint4(to_tf32(wv.x), to_tf32(wv.y), to_tf32(wv.z), to_tf32(wv.w));
            *(uint4*)&sW[j][kq] = cv;
        }
        // H tile: 64 x 32
        for (int i = t; i < 512; i += 256) {
            int m = i >> 3, kq = (i & 7) * 4;
            float4 hv = *(const float4*)&h[(n0 + m) * 128 + kk + kq];
            uint4 cv = make_uint4(to_tf32(hv.x), to_tf32(hv.y), to_tf32(hv.z), to_tf32(hv.w));
            *(uint4*)&sH[m][kq] = cv;
        }
        __syncthreads();
        #pragma unroll
        for (int ks = 0; ks < 4; ks++) {
            int kc = ks * 8 + lane4;
            int row = warp_m * 16 + quad;
            unsigned a0 = sH[row][kc];
            unsigned a1 = sH[row + 8][kc];
            unsigned a2 = sH[row][kc + 4];
            unsigned a3 = sH[row + 8][kc + 4];
            #pragma unroll
            for (int nt = 0; nt < 8; nt++) {
                int ncol = warp_n * 64 + nt * 8 + quad;
                unsigned b0 = sW[ncol][kc];
                unsigned b1 = sW[ncol][kc + 4];
                asm volatile(
                    "mma.sync.aligned.m16n8k8.row.col.f32.tf32.tf32.f32 "
                    "{%0,%1,%2,%3}, {%4,%5,%6,%7}, {%8,%9}, {%0,%1,%2,%3};"
                    : "+f"(acc[nt][0]), "+f"(acc[nt][1]), "+f"(acc[nt][2]), "+f"(acc[nt][3])
                    : "r"(a0), "r"(a1), "r"(a2), "r"(a3), "r"(b0), "r"(b1));
            }
        }
        __syncthreads();
    }

    // epilogue: store xp (float2 per row per ntile) + fused attention dot products
    int r0g = n0 + warp_m * 16 + quad;
    int r1g = r0g + 8;
    int cbase = warp_n * 64;
    float ps0h0 = 0.f, ps0h1 = 0.f, ps1h0 = 0.f, ps1h1 = 0.f;
    float pd0h0 = 0.f, pd0h1 = 0.f, pd1h0 = 0.f, pd1h1 = 0.f;
    #pragma unroll
    for (int nt = 0; nt < 8; nt++) {
        int col = cbase + nt * 8 + lane4 * 2;
        float2 as2 = *(const float2*)&As[col];
        float2 ad2 = *(const float2*)&Ad[col];
        *(float2*)&xp[r0g * 128 + col] = make_float2(acc[nt][0], acc[nt][1]);
        *(float2*)&xp[r1g * 128 + col] = make_float2(acc[nt][2], acc[nt][3]);
        float p0 = acc[nt][0] * as2.x + acc[nt][1] * as2.y;
        float p1 = acc[nt][2] * as2.x + acc[nt][3] * as2.y;
        float q0 = acc[nt][0] * ad2.x + acc[nt][1] * ad2.y;
        float q1 = acc[nt][2] * ad2.x + acc[nt][3] * ad2.y;
        if (nt < 4) { ps0h0 += p0; ps1h0 += p1; pd0h0 += q0; pd1h0 += q1; }
        else        { ps0h1 += p0; ps1h1 += p1; pd0h1 += q0; pd1h1 += q1; }
    }
    #pragma unroll
    for (int off = 1; off <= 2; off <<= 1) {
        ps0h0 += __shfl_xor_sync(0xffffffff, ps0h0, off);
        ps0h1 += __shfl_xor_sync(0xffffffff, ps0h1, off);
        ps1h0 += __shfl_xor_sync(0xffffffff, ps1h0, off);
        ps1h1 += __shfl_xor_sync(0xffffffff, ps1h1, off);
        pd0h0 += __shfl_xor_sync(0xffffffff, pd0h0, off);
        pd0h1 += __shfl_xor_sync(0xffffffff, pd0h1, off);
        pd1h0 += __shfl_xor_sync(0xffffffff, pd1h0, off);
        pd1h1 += __shfl_xor_sync(0xffffffff, pd1h1, off);
    }
    if (lane4 == 0) {
        int h0 = warp_n * 2, h1 = h0 + 1;
        asn[r0g * 4 + h0] = ps0h0; asn[r0g * 4 + h1] = ps0h1;
        asn[r1g * 4 + h0] = ps1h0; asn[r1g * 4 + h1] = ps1h1;
        adn[r0g * 4 + h0] = pd0h0; adn[r0g * 4 + h1] = pd0h1;
        adn[r1g * 4 + h0] = pd1h0; adn[r1g * 4 + h1] = pd1h1;
    }
}

// ---------------- aggregation: warp-per-node online softmax over CSR ----------------
__global__ void k_aggr(const float* __restrict__ xp, const float* __restrict__ asn,
                       const float* __restrict__ adn,
                       const float* __restrict__ biasP, const float* __restrict__ biasL,
                       const int* __restrict__ indptr, const int* __restrict__ csr,
                       float* __restrict__ hout, int Np, int NpPad, int Nl) {
    int n = (blockIdx.x * blockDim.x + threadIdx.x) >> 5;
    int lane = threadIdx.x & 31;
    const float* bias;
    if (n < NpPad) { if (n >= Np) return; bias = biasP; }
    else { if (n - NpPad >= Nl) return; bias = biasL; }
    int hd = lane >> 3;
    int j = lane * 4;
    int base = indptr[n], end = indptr[n + 1];
    float adn_n = adn[n * 4 + hd];
    float mymax = -1e30f, denom = 0.f;
    float4 acc = make_float4(0.f, 0.f, 0.f, 0.f);
    int src = csr[base];
    float4 xv = *(const float4*)&xp[src * 128 + j];
    float av = asn[src * 4 + hd];
    for (int i = base; i < end; i++) {
        float4 nxv; float nav;
        if (i + 1 < end) {
            int nsrc = csr[i + 1];
            nxv = *(const float4*)&xp[nsrc * 128 + j];
            nav = asn[nsrc * 4 + hd];
        }
        float e = av + adn_n;
        e = (e >= 0.f) ? e : 0.2f * e;                 // leaky_relu 0.2
        float nm = fmaxf(mymax, e);
        float corr = __expf(mymax - nm);               // 0 on first edge
        float w = __expf(e - nm);
        denom = denom * corr + w;
        acc.x = acc.x * corr + w * xv.x;
        acc.y = acc.y * corr + w * xv.y;
        acc.z = acc.z * corr + w * xv.z;
        acc.w = acc.w * corr + w * xv.w;
        mymax = nm;
        xv = nxv; av = nav;
    }
    float inv = 1.f / (denom + 1e-16f);
    float4 o;
    o.x = fmaxf(acc.x * inv + bias[j + 0], 0.f);
    o.y = fmaxf(acc.y * inv + bias[j + 1], 0.f);
    o.z = fmaxf(acc.z * inv + bias[j + 2], 0.f);
    o.w = fmaxf(acc.w * inv + bias[j + 3], 0.f);
    *(float4*)&hout[n * 128 + j] = o;
}

// ---------------- pooling ----------------
__global__ void k_pool(const float* __restrict__ h, const int* __restrict__ pb,
                       const int* __restrict__ lb, float* pool, int* gc,
                       int Np, int NpPad, int Nl) {
    int j = threadIdx.x;  // 128
    int n0 = blockIdx.x * 64;
    int nend = n0 + 64;
    int curg = -1;
    float acc = 0.f;
    int cacc = 0;
    for (int n = n0; n < nend; n++) {
        int g;
        if (n < Np) g = pb[n];
        else if (n >= NpPad && (n - NpPad) < Nl) g = G + lb[n - NpPad];
        else continue;
        if (g != curg) {
            if (curg >= 0) {
                atomicAdd(&pool[curg * HID + j], acc);
                if (j == 0) atomicAdd(&gc[curg], cacc);
            }
            curg = g; acc = 0.f; cacc = 0;
        }
        acc += h[n * HID + j];
        cacc++;
    }
    if (curg >= 0) {
        atomicAdd(&pool[curg * HID + j], acc);
        if (j == 0) atomicAdd(&gc[curg], cacc);
    }
}

// ---------------- prediction MLP ----------------
__global__ void k_mlp1(const float* __restrict__ pool, const int* __restrict__ gc,
                       const float* __restrict__ w, const float* __restrict__ b,
                       float* __restrict__ out) {
    int g = blockIdx.x, o = threadIdx.x;  // 256 threads
    __shared__ float jv[256];
    if (o < 128) {
        float c = fmaxf((float)gc[g], 1.f);
        jv[o] = pool[g * HID + o] / c;
    } else {
        float c = fmaxf((float)gc[G + g], 1.f);
        jv[o] = pool[(G + g) * HID + (o - 128)] / c;
    }
    __syncthreads();
    float s = b[o];
    #pragma unroll 8
    for (int c2 = 0; c2 < 256; c2++) s += jv[c2] * w[o * 256 + c2];
    out[g * 256 + o] = fmaxf(s, 0.f);
}
__global__ void k_mlp2(const float* __restrict__ in, const float* __restrict__ w,
                       const float* __restrict__ b, float* __restrict__ out) {
    int g = blockIdx.x, o = threadIdx.x;  // 128 threads
    __shared__ float jv[256];
    jv[o] = in[g * 256 + o];
    jv[o + 128] = in[g * 256 + o + 128];
    __syncthreads();
    float s = b[o];
    #pragma unroll 8
    for (int c2 = 0; c2 < 256; c2++) s += jv[c2] * w[o * 256 + c2];
    out[g * 128 + o] = fmaxf(s, 0.f);
}
__global__ void k_mlp3(const float* __restrict__ in, const float* __restrict__ w,
                       const float* __restrict__ b, float* __restrict__ out) {
    int g = threadIdx.x;
    if (g < G) {
        float s = b[0];
        #pragma unroll 8
        for (int c = 0; c < 128; c++) s += in[g * 128 + c] * w[c];
        out[g] = s;
    }
}

// ---------------- launch ----------------
extern "C" void kernel_launch(void* const* d_in, const int* in_sizes, int n_in,
                              void* d_out, int out_size) {
    const float* px  = (const float*)d_in[0];
    const int*   pei = (const int*)d_in[1];
    const int*   pb  = (const int*)d_in[2];
    const float* lx  = (const float*)d_in[3];
    const int*   lei = (const int*)d_in[4];
    const int*   lb  = (const int*)d_in[5];
    const float* tw1 = (const float*)d_in[6];
    const float* tb1 = (const float*)d_in[7];
    const float* tw2 = (const float*)d_in[8];
    const float* tb2 = (const float*)d_in[9];
    const float* pew = (const float*)d_in[10];
    const float* peb = (const float*)d_in[11];
    const float* lew = (const float*)d_in[12];
    const float* leb = (const float*)d_in[13];
    const float* pgW = (const float*)d_in[14];
    const float* pgs = (const float*)d_in[15];
    const float* pgd = (const float*)d_in[16];
    const float* pgb = (const float*)d_in[17];
    const float* lgW = (const float*)d_in[18];
    const float* lgs = (const float*)d_in[19];
    const float* lgd = (const float*)d_in[20];
    const float* lgb = (const float*)d_in[21];
    const float* prw1 = (const float*)d_in[22];
    const float* prb1 = (const float*)d_in[23];
    const float* prw2 = (const float*)d_in[24];
    const float* prb2 = (const float*)d_in[25];
    const float* prw3 = (const float*)d_in[26];
    const float* prb3 = (const float*)d_in[27];

    int Np = in_sizes[0] / 16, Ep = in_sizes[1] / 2;
    int Nl = in_sizes[3] / 16, El = in_sizes[4] / 2;
    int NpPad = (Np + 63) / 64 * 64;
    int NT = NpPad + (Nl + 63) / 64 * 64;
    int Etot = Ep + El;

    float *h0, *h1, *xp, *asn, *adn, *temb, *pool, *m1, *m2;
    int *cnt, *cur, *indptr, *csr, *gc;
    cudaGetSymbolAddress((void**)&h0, g_h0);
    cudaGetSymbolAddress((void**)&h1, g_h1);
    cudaGetSymbolAddress((void**)&xp, g_xp);
    cudaGetSymbolAddress((void**)&asn, g_asn);
    cudaGetSymbolAddress((void**)&adn, g_adn);
    cudaGetSymbolAddress((void**)&temb, g_temb);
    cudaGetSymbolAddress((void**)&pool, g_pool);
    cudaGetSymbolAddress((void**)&m1, g_m1);
    cudaGetSymbolAddress((void**)&m2, g_m2);
    cudaGetSymbolAddress((void**)&cnt, g_cnt);
    cudaGetSymbolAddress((void**)&cur, g_cur);
    cudaGetSymbolAddress((void**)&indptr, g_indptr);
    cudaGetSymbolAddress((void**)&csr, g_csr);
    cudaGetSymbolAddress((void**)&gc, g_gcnt);

    const int* pdst = pei + Ep;
    const int* ldst = lei + El;

    int setup_work = NT > 2 * G * HID ? NT : 2 * G * HID;
    k_setup<<<1 + (setup_work + 255) / 256, 256>>>(tw1, tb1, tw2, tb2, temb,
                                                   cnt, cur, pool, gc, Np, NpPad, Nl, NT);
    k_count<<<(Etot + 255) / 256, 256>>>(pdst, ldst, cnt, Ep, El, NpPad);
    k_scan<<<1, 1024>>>(cnt, indptr, NT);
    int sf_work = NT > Etot ? NT : Etot;
    k_selffill<<<(sf_work + 255) / 256, 256>>>(pei, pdst, lei, ldst, indptr, cur, csr,
                                               Ep, El, Np, NpPad, Nl, NT);
    int nbP32 = NpPad / 32, nbL32 = (Nl + 31) / 32;
    k_encode<<<nbP32 + nbL32, 256>>>(px, lx, pew, peb, lew, leb, temb, h0,
                                     Np, NpPad, Nl, nbP32);

    int nbP64 = NpPad / 64, nbL64 = (Nl + 63) / 64;
    int nAggr = NpPad + Nl;
    int aggrBlocks = (nAggr * 32 + 255) / 256;
    float* hin = h0;
    float* hout = h1;
    for (int l = 0; l < DEPTH; l++) {
        k_gemm_attn<<<nbP64 + nbL64, 256>>>(hin,
            pgW + l * HID * HID, lgW + l * HID * HID,
            pgs + l * HID, pgd + l * HID, lgs + l * HID, lgd + l * HID,
            xp, asn, adn, NpPad, nbP64);
        k_aggr<<<aggrBlocks, 256>>>(xp, asn, adn, pgb + l * HID, lgb + l * HID,
                                    indptr, csr, hout, Np, NpPad, Nl);
        float* tmp = hin; hin = hout; hout = tmp;
    }

    k_pool<<<(NT + 63) / 64, 128>>>(hin, pb, lb, pool, gc, Np, NpPad, Nl);

    k_mlp1<<<G, 256>>>(pool, gc, prw1, prb1, m1);
    k_mlp2<<<G, 128>>>(m1, prw2, prb2, m2);
    k_mlp3<<<1, 32>>>(m2, prw3, prb3, (float*)d_out);
}

// round 6
// speedup vs baseline: 1.6798x; 1.0937x over previous
#include <cuda_runtime.h>
#include <math.h>

#define HID 128
#define G 32
#define DEPTH 4
#define N_MAX 46080
#define E_MAX 640000

// ---------------- scratch ----------------
__device__ float g_h0[N_MAX * HID];
__device__ float g_h1[N_MAX * HID];
__device__ float g_xp[N_MAX * HID];
__device__ float g_asn[N_MAX * 4];
__device__ float g_adn[N_MAX * 4];
__device__ int   g_cnt[N_MAX];
__device__ int   g_cur[N_MAX];
__device__ int   g_indptr[N_MAX];
__device__ int   g_csr[E_MAX];
__device__ int   g_total[1];
__device__ float g_temb[HID];
__device__ float g_pool[2 * G * HID];
__device__ int   g_gcnt[2 * G];
__device__ float g_m2[G * HID];

__device__ __forceinline__ unsigned to_tf32(float x) {
    unsigned r;
    asm("cvt.rna.tf32.f32 %0, %1;" : "=r"(r) : "f"(x));
    return r;
}

// ---------------- setup: temb (block 0) + cnt/cur/pool/gcnt/total init ----------------
__global__ void k_setup(const float* __restrict__ w1, const float* __restrict__ b1,
                        const float* __restrict__ w2, const float* __restrict__ b2,
                        float* __restrict__ temb,
                        int* __restrict__ cnt, int* __restrict__ cur,
                        float* __restrict__ pool, int* __restrict__ gc, int* __restrict__ total,
                        int Np, int NpPad, int Nl, int NT) {
    int t = threadIdx.x;
    if (blockIdx.x == 0) {
        if (t == 0) total[0] = 0;
        __shared__ float u[128];
        if (t < 128) {
            float s = b1[t];
            #pragma unroll
            for (int k = 16; k < 32; k++) s += w1[t * 32 + k];
            u[t] = s / (1.f + expf(-s));
        }
        __syncthreads();
        if (t < 128) {
            float o = b2[t];
            #pragma unroll 8
            for (int i = 0; i < 128; i++) o += u[i] * w2[t * 128 + i];
            temb[t] = o;
        }
        return;
    }
    int i = (blockIdx.x - 1) * 256 + t;
    if (i < NT) {
        bool valid = (i < Np) || (i >= NpPad && (i - NpPad) < Nl);
        cnt[i] = valid ? 1 : 0;   // slot 0 reserved for self-loop
        cur[i] = valid ? 1 : 0;
    }
    if (i < 2 * G * HID) pool[i] = 0.f;
    if (i < 2 * G) gc[i] = 0;
}

// ---------------- CSR: count ----------------
__global__ void k_count(const int* __restrict__ pdst, const int* __restrict__ ldst,
                        int* cnt, int Ep, int El, int NpPad) {
    int i = blockIdx.x * blockDim.x + threadIdx.x;
    if (i < Ep) atomicAdd(&cnt[pdst[i]], 1);
    else if (i < Ep + El) atomicAdd(&cnt[ldst[i - Ep] + NpPad], 1);
}

// ---------------- CSR: parallel segment allocation (block scan + atomic base) ------
// Also writes the self-loop entry at csr[base]. indptr non-monotonic across blocks
// (fine: aggr uses indptr[n] + cnt[n]).
__global__ void k_alloc(const int* __restrict__ cnt, int* __restrict__ indptr,
                        int* __restrict__ csr, int* __restrict__ total,
                        int Np, int NpPad, int Nl, int NT) {
    int t = threadIdx.x;
    int i = blockIdx.x * 256 + t;
    int lane = t & 31, w = t >> 5;
    bool inr = (i < NT);
    bool valid = inr && ((i < Np) || (i >= NpPad && (i - NpPad) < Nl));
    int c = inr ? cnt[i] : 0;
    // warp inclusive scan
    int v = c;
    #pragma unroll
    for (int off = 1; off < 32; off <<= 1) {
        int u = __shfl_up_sync(0xffffffff, v, off);
        if (lane >= off) v += u;
    }
    __shared__ int wt[8];
    __shared__ int sbase;
    if (lane == 31) wt[w] = v;
    __syncthreads();
    if (t < 8) {
        int x = wt[t];
        #pragma unroll
        for (int off = 1; off < 8; off <<= 1) {
            int u = __shfl_up_sync(0xff, x, off);
            if (t >= off) x += u;
        }
        wt[t] = x;
        if (t == 7) sbase = atomicAdd(total, x);
    }
    __syncthreads();
    int excl = sbase + (v - c) + (w ? wt[w - 1] : 0);
    if (inr) {
        indptr[i] = excl;
        if (valid) csr[excl] = i;   // self-loop at slot 0
    }
}

// ---------------- CSR: edge fill ----------------
__global__ void k_fill(const int* __restrict__ psrc, const int* __restrict__ pdst,
                       const int* __restrict__ lsrc, const int* __restrict__ ldst,
                       const int* __restrict__ indptr, int* cur, int* __restrict__ csr,
                       int Ep, int El, int NpPad) {
    int i = blockIdx.x * blockDim.x + threadIdx.x;
    if (i < Ep) {
        int d = pdst[i];
        int p = indptr[d] + atomicAdd(&cur[d], 1);
        csr[p] = psrc[i];
    } else if (i < Ep + El) {
        int e = i - Ep;
        int d = ldst[e] + NpPad;
        int p = indptr[d] + atomicAdd(&cur[d], 1);
        csr[p] = lsrc[e] + NpPad;
    }
}

// ---------------- encoder ----------------
__global__ void k_encode(const float* __restrict__ px, const float* __restrict__ lx,
                         const float* __restrict__ pew, const float* __restrict__ peb,
                         const float* __restrict__ lew, const float* __restrict__ leb,
                         const float* __restrict__ temb, float* __restrict__ h,
                         int Np, int NpPad, int Nl, int nbP) {
    __shared__ float sw[128 * 16];
    __shared__ float sb[128];
    __shared__ float sx[32 * 16];
    int t = threadIdx.x;
    int blk = blockIdx.x;
    const float* x; const float* ew; const float* ebp;
    int n0, Nv, base;
    if (blk < nbP) { x = px; ew = pew; ebp = peb; n0 = blk * 32; Nv = Np; base = 0; }
    else { x = lx; ew = lew; ebp = leb; n0 = NpPad + (blk - nbP) * 32; Nv = Nl; base = NpPad; }
    for (int i = t; i < 2048; i += 256) sw[i] = ew[i];
    if (t < 128) sb[t] = ebp[t] + temb[t];
    for (int i = t; i < 512; i += 256) {
        int m = i >> 4;
        int loc = n0 - base + m;
        sx[i] = (loc < Nv) ? x[loc * 16 + (i & 15)] : 0.f;
    }
    __syncthreads();
    for (int idx = t; idx < 32 * 128; idx += 256) {
        int m = idx >> 7, j = idx & 127;
        float s = sb[j];
        #pragma unroll
        for (int k = 0; k < 16; k++) s += sx[m * 16 + k] * sw[j * 16 + k];
        h[(n0 + m) * 128 + j] = s;
    }
}

// ---------------- tf32 tensor-core GEMM 64x128 + fused attention coefficients ----
__global__ void __launch_bounds__(256) k_gemm_attn(
        const float* __restrict__ h,
        const float* __restrict__ Wp, const float* __restrict__ Wl,
        const float* __restrict__ asp, const float* __restrict__ adp,
        const float* __restrict__ asl, const float* __restrict__ adl,
        float* __restrict__ xp, float* __restrict__ asn, float* __restrict__ adn,
        int NpPad, int nbP) {
    __shared__ unsigned sH[64][36];
    __shared__ unsigned sW[128][36];
    int t = threadIdx.x;
    int blk = blockIdx.x;
    const float* W; const float* As; const float* Ad;
    int n0;
    if (blk < nbP) { W = Wp; As = asp; Ad = adp; n0 = blk * 64; }
    else { W = Wl; As = asl; Ad = adl; n0 = NpPad + (blk - nbP) * 64; }

    int wid = t >> 5;
    int lane = t & 31;
    int warp_m = wid >> 1;
    int warp_n = wid & 1;
    int quad = lane >> 2;
    int lane4 = lane & 3;

    float acc[8][4];
    #pragma unroll
    for (int i = 0; i < 8; i++)
        #pragma unroll
        for (int j = 0; j < 4; j++) acc[i][j] = 0.f;

    for (int kk = 0; kk < 128; kk += 32) {
        for (int i = t; i < 1024; i += 256) {
            int j = i >> 3, kq = (i & 7) * 4;
            float4 wv = *(const float4*)&W[j * 128 + kk + kq];
            uint4 cv = make_uint4(to_tf32(wv.x), to_tf32(wv.y), to_tf32(wv.z), to_tf32(wv.w));
            *(uint4*)&sW[j][kq] = cv;
        }
        for (int i = t; i < 512; i += 256) {
            int m = i >> 3, kq = (i & 7) * 4;
            float4 hv = *(const float4*)&h[(n0 + m) * 128 + kk + kq];
            uint4 cv = make_uint4(to_tf32(hv.x), to_tf32(hv.y), to_tf32(hv.z), to_tf32(hv.w));
            *(uint4*)&sH[m][kq] = cv;
        }
        __syncthreads();
        #pragma unroll
        for (int ks = 0; ks < 4; ks++) {
            int kc = ks * 8 + lane4;
            int row = warp_m * 16 + quad;
            unsigned a0 = sH[row][kc];
            unsigned a1 = sH[row + 8][kc];
            unsigned a2 = sH[row][kc + 4];
            unsigned a3 = sH[row + 8][kc + 4];
            #pragma unroll
            for (int nt = 0; nt < 8; nt++) {
                int ncol = warp_n * 64 + nt * 8 + quad;
                unsigned b0 = sW[ncol][kc];
                unsigned b1 = sW[ncol][kc + 4];
                asm volatile(
                    "mma.sync.aligned.m16n8k8.row.col.f32.tf32.tf32.f32 "
                    "{%0,%1,%2,%3}, {%4,%5,%6,%7}, {%8,%9}, {%0,%1,%2,%3};"
                    : "+f"(acc[nt][0]), "+f"(acc[nt][1]), "+f"(acc[nt][2]), "+f"(acc[nt][3])
                    : "r"(a0), "r"(a1), "r"(a2), "r"(a3), "r"(b0), "r"(b1));
            }
        }
        __syncthreads();
    }

    int r0g = n0 + warp_m * 16 + quad;
    int r1g = r0g + 8;
    int cbase = warp_n * 64;
    float ps0h0 = 0.f, ps0h1 = 0.f, ps1h0 = 0.f, ps1h1 = 0.f;
    float pd0h0 = 0.f, pd0h1 = 0.f, pd1h0 = 0.f, pd1h1 = 0.f;
    #pragma unroll
    for (int nt = 0; nt < 8; nt++) {
        int col = cbase + nt * 8 + lane4 * 2;
        float2 as2 = *(const float2*)&As[col];
        float2 ad2 = *(const float2*)&Ad[col];
        *(float2*)&xp[r0g * 128 + col] = make_float2(acc[nt][0], acc[nt][1]);
        *(float2*)&xp[r1g * 128 + col] = make_float2(acc[nt][2], acc[nt][3]);
        float p0 = acc[nt][0] * as2.x + acc[nt][1] * as2.y;
        float p1 = acc[nt][2] * as2.x + acc[nt][3] * as2.y;
        float q0 = acc[nt][0] * ad2.x + acc[nt][1] * ad2.y;
        float q1 = acc[nt][2] * ad2.x + acc[nt][3] * ad2.y;
        if (nt < 4) { ps0h0 += p0; ps1h0 += p1; pd0h0 += q0; pd1h0 += q1; }
        else        { ps0h1 += p0; ps1h1 += p1; pd0h1 += q0; pd1h1 += q1; }
    }
    #pragma unroll
    for (int off = 1; off <= 2; off <<= 1) {
        ps0h0 += __shfl_xor_sync(0xffffffff, ps0h0, off);
        ps0h1 += __shfl_xor_sync(0xffffffff, ps0h1, off);
        ps1h0 += __shfl_xor_sync(0xffffffff, ps1h0, off);
        ps1h1 += __shfl_xor_sync(0xffffffff, ps1h1, off);
        pd0h0 += __shfl_xor_sync(0xffffffff, pd0h0, off);
        pd0h1 += __shfl_xor_sync(0xffffffff, pd0h1, off);
        pd1h0 += __shfl_xor_sync(0xffffffff, pd1h0, off);
        pd1h1 += __shfl_xor_sync(0xffffffff, pd1h1, off);
    }
    if (lane4 == 0) {
        int h0 = warp_n * 2, h1 = h0 + 1;
        asn[r0g * 4 + h0] = ps0h0; asn[r0g * 4 + h1] = ps0h1;
        asn[r1g * 4 + h0] = ps1h0; asn[r1g * 4 + h1] = ps1h1;
        adn[r0g * 4 + h0] = pd0h0; adn[r0g * 4 + h1] = pd0h1;
        adn[r1g * 4 + h0] = pd1h0; adn[r1g * 4 + h1] = pd1h1;
    }
}

// ---------------- aggregation: warp-per-node online softmax, 2-deep prefetch ------
__global__ void k_aggr(const float* __restrict__ xp, const float* __restrict__ asn,
                       const float* __restrict__ adn,
                       const float* __restrict__ biasP, const float* __restrict__ biasL,
                       const int* __restrict__ indptr, const int* __restrict__ cnt,
                       const int* __restrict__ csr,
                       float* __restrict__ hout, int Np, int NpPad, int Nl) {
    int n = (blockIdx.x * blockDim.x + threadIdx.x) >> 5;
    int lane = threadIdx.x & 31;
    const float* bias;
    if (n < NpPad) { if (n >= Np) return; bias = biasP; }
    else { if (n - NpPad >= Nl) return; bias = biasL; }
    int hd = lane >> 3;
    int j = lane * 4;
    int base = indptr[n];
    int deg = cnt[n];
    float adn_n = adn[n * 4 + hd];
    float mymax = -1e30f, denom = 0.f;
    float4 acc = make_float4(0.f, 0.f, 0.f, 0.f);
    // 2-deep pipeline
    float4 xv0, xv1; float av0 = 0.f, av1 = 0.f;
    {
        int s0 = csr[base];
        xv0 = *(const float4*)&xp[s0 * 128 + j];
        av0 = asn[s0 * 4 + hd];
    }
    if (deg > 1) {
        int s1 = csr[base + 1];
        xv1 = *(const float4*)&xp[s1 * 128 + j];
        av1 = asn[s1 * 4 + hd];
    }
    for (int i = 0; i < deg; i++) {
        float4 xv2; float av2;
        if (i + 2 < deg) {
            int s2 = csr[base + i + 2];
            xv2 = *(const float4*)&xp[s2 * 128 + j];
            av2 = asn[s2 * 4 + hd];
        }
        float e = av0 + adn_n;
        e = (e >= 0.f) ? e : 0.2f * e;                 // leaky_relu 0.2
        float nm = fmaxf(mymax, e);
        float corr = __expf(mymax - nm);               // 0 on first edge
        float w = __expf(e - nm);
        denom = denom * corr + w;
        acc.x = acc.x * corr + w * xv0.x;
        acc.y = acc.y * corr + w * xv0.y;
        acc.z = acc.z * corr + w * xv0.z;
        acc.w = acc.w * corr + w * xv0.w;
        mymax = nm;
        xv0 = xv1; av0 = av1;
        xv1 = xv2; av1 = av2;
    }
    float inv = 1.f / (denom + 1e-16f);
    float4 o;
    o.x = fmaxf(acc.x * inv + bias[j + 0], 0.f);
    o.y = fmaxf(acc.y * inv + bias[j + 1], 0.f);
    o.z = fmaxf(acc.z * inv + bias[j + 2], 0.f);
    o.w = fmaxf(acc.w * inv + bias[j + 3], 0.f);
    *(float4*)&hout[n * 128 + j] = o;
}

// ---------------- pooling ----------------
__global__ void k_pool(const float* __restrict__ h, const int* __restrict__ pb,
                       const int* __restrict__ lb, float* pool, int* gc,
                       int Np, int NpPad, int Nl) {
    int j = threadIdx.x;  // 128
    int n0 = blockIdx.x * 64;
    int nend = n0 + 64;
    int curg = -1;
    float acc = 0.f;
    int cacc = 0;
    for (int n = n0; n < nend; n++) {
        int g;
        if (n < Np) g = pb[n];
        else if (n >= NpPad && (n - NpPad) < Nl) g = G + lb[n - NpPad];
        else continue;
        if (g != curg) {
            if (curg >= 0) {
                atomicAdd(&pool[curg * HID + j], acc);
                if (j == 0) atomicAdd(&gc[curg], cacc);
            }
            curg = g; acc = 0.f; cacc = 0;
        }
        acc += h[n * HID + j];
        cacc++;
    }
    if (curg >= 0) {
        atomicAdd(&pool[curg * HID + j], acc);
        if (j == 0) atomicAdd(&gc[curg], cacc);
    }
}

// ---------------- prediction MLP: layers 1+2 fused per group ----------------
__global__ void k_mlp12(const float* __restrict__ pool, const int* __restrict__ gc,
                        const float* __restrict__ w1, const float* __restrict__ b1,
                        const float* __restrict__ w2, const float* __restrict__ b2,
                        float* __restrict__ out2) {
    int g = blockIdx.x, o = threadIdx.x;  // 256 threads
    __shared__ float jv[256];
    __shared__ float h1[256];
    if (o < 128) {
        float c = fmaxf((float)gc[g], 1.f);
        jv[o] = pool[g * HID + o] / c;
    } else {
        float c = fmaxf((float)gc[G + g], 1.f);
        jv[o] = pool[(G + g) * HID + (o - 128)] / c;
    }
    __syncthreads();
    float s = b1[o];
    #pragma unroll 8
    for (int c2 = 0; c2 < 256; c2++) s += jv[c2] * w1[o * 256 + c2];
    h1[o] = fmaxf(s, 0.f);
    __syncthreads();
    if (o < 128) {
        float s2 = b2[o];
        #pragma unroll 8
        for (int c2 = 0; c2 < 256; c2++) s2 += h1[c2] * w2[o * 256 + c2];
        out2[g * 128 + o] = fmaxf(s2, 0.f);
    }
}
__global__ void k_mlp3(const float* __restrict__ in, const float* __restrict__ w,
                       const float* __restrict__ b, float* __restrict__ out) {
    int g = threadIdx.x;
    if (g < G) {
        float s = b[0];
        #pragma unroll 8
        for (int c = 0; c < 128; c++) s += in[g * 128 + c] * w[c];
        out[g] = s;
    }
}

// ---------------- launch ----------------
extern "C" void kernel_launch(void* const* d_in, const int* in_sizes, int n_in,
                              void* d_out, int out_size) {
    const float* px  = (const float*)d_in[0];
    const int*   pei = (const int*)d_in[1];
    const int*   pb  = (const int*)d_in[2];
    const float* lx  = (const float*)d_in[3];
    const int*   lei = (const int*)d_in[4];
    const int*   lb  = (const int*)d_in[5];
    const float* tw1 = (const float*)d_in[6];
    const float* tb1 = (const float*)d_in[7];
    const float* tw2 = (const float*)d_in[8];
    const float* tb2 = (const float*)d_in[9];
    const float* pew = (const float*)d_in[10];
    const float* peb = (const float*)d_in[11];
    const float* lew = (const float*)d_in[12];
    const float* leb = (const float*)d_in[13];
    const float* pgW = (const float*)d_in[14];
    const float* pgs = (const float*)d_in[15];
    const float* pgd = (const float*)d_in[16];
    const float* pgb = (const float*)d_in[17];
    const float* lgW = (const float*)d_in[18];
    const float* lgs = (const float*)d_in[19];
    const float* lgd = (const float*)d_in[20];
    const float* lgb = (const float*)d_in[21];
    const float* prw1 = (const float*)d_in[22];
    const float* prb1 = (const float*)d_in[23];
    const float* prw2 = (const float*)d_in[24];
    const float* prb2 = (const float*)d_in[25];
    const float* prw3 = (const float*)d_in[26];
    const float* prb3 = (const float*)d_in[27];

    int Np = in_sizes[0] / 16, Ep = in_sizes[1] / 2;
    int Nl = in_sizes[3] / 16, El = in_sizes[4] / 2;
    int NpPad = (Np + 63) / 64 * 64;
    int NT = NpPad + (Nl + 63) / 64 * 64;
    int Etot = Ep + El;

    float *h0, *h1, *xp, *asn, *adn, *temb, *pool, *m2;
    int *cnt, *cur, *indptr, *csr, *gc, *total;
    cudaGetSymbolAddress((void**)&h0, g_h0);
    cudaGetSymbolAddress((void**)&h1, g_h1);
    cudaGetSymbolAddress((void**)&xp, g_xp);
    cudaGetSymbolAddress((void**)&asn, g_asn);
    cudaGetSymbolAddress((void**)&adn, g_adn);
    cudaGetSymbolAddress((void**)&temb, g_temb);
    cudaGetSymbolAddress((void**)&pool, g_pool);
    cudaGetSymbolAddress((void**)&m2, g_m2);
    cudaGetSymbolAddress((void**)&cnt, g_cnt);
    cudaGetSymbolAddress((void**)&cur, g_cur);
    cudaGetSymbolAddress((void**)&indptr, g_indptr);
    cudaGetSymbolAddress((void**)&csr, g_csr);
    cudaGetSymbolAddress((void**)&gc, g_gcnt);
    cudaGetSymbolAddress((void**)&total, g_total);

    const int* pdst = pei + Ep;
    const int* ldst = lei + El;

    int setup_work = NT > 2 * G * HID ? NT : 2 * G * HID;
    k_setup<<<1 + (setup_work + 255) / 256, 256>>>(tw1, tb1, tw2, tb2, temb,
                                                   cnt, cur, pool, gc, total,
                                                   Np, NpPad, Nl, NT);
    k_count<<<(Etot + 255) / 256, 256>>>(pdst, ldst, cnt, Ep, El, NpPad);
    k_alloc<<<(NT + 255) / 256, 256>>>(cnt, indptr, csr, total, Np, NpPad, Nl, NT);
    k_fill<<<(Etot + 255) / 256, 256>>>(pei, pdst, lei, ldst, indptr, cur, csr,
                                        Ep, El, NpPad);
    int nbP32 = NpPad / 32, nbL32 = (Nl + 31) / 32;
    k_encode<<<nbP32 + nbL32, 256>>>(px, lx, pew, peb, lew, leb, temb, h0,
                                     Np, NpPad, Nl, nbP32);

    int nbP64 = NpPad / 64, nbL64 = (Nl + 63) / 64;
    int nAggr = NpPad + Nl;
    int aggrBlocks = (nAggr * 32 + 255) / 256;
    float* hin = h0;
    float* hout = h1;
    for (int l = 0; l < DEPTH; l++) {
        k_gemm_attn<<<nbP64 + nbL64, 256>>>(hin,
            pgW + l * HID * HID, lgW + l * HID * HID,
            pgs + l * HID, pgd + l * HID, lgs + l * HID, lgd + l * HID,
            xp, asn, adn, NpPad, nbP64);
        k_aggr<<<aggrBlocks, 256>>>(xp, asn, adn, pgb + l * HID, lgb + l * HID,
                                    indptr, cnt, csr, hout, Np, NpPad, Nl);
        float* tmp = hin; hin = hout; hout = tmp;
    }

    k_pool<<<(NT + 63) / 64, 128>>>(hin, pb, lb, pool, gc, Np, NpPad, Nl);

    k_mlp12<<<G, 256>>>(pool, gc, prw1, prb1, prw2, prb2, m2);
    k_mlp3<<<1, 32>>>(m2, prw3, prb3, (float*)d_out);
}

// round 8
// speedup vs baseline: 1.7487x; 1.0410x over previous
#include <cuda_runtime.h>
#include <cuda_fp16.h>
#include <math.h>

#define HID 128
#define G 32
#define DEPTH 4
#define N_MAX 46080
#define E_MAX 640000

// ---------------- scratch ----------------
__device__ float  g_h0[N_MAX * HID];
__device__ float  g_h1[N_MAX * HID];
__device__ __half g_xph[N_MAX * HID];
__device__ float  g_asn[N_MAX * 4];
__device__ float  g_adn[N_MAX * 4];
__device__ int    g_cnt[N_MAX];
__device__ int    g_cur[N_MAX];
__device__ int    g_indptr[N_MAX];
__device__ int    g_csr[E_MAX];
__device__ int    g_total[1];
__device__ float  g_temb[HID];
__device__ float  g_pool[2 * G * HID];
__device__ int    g_gcnt[2 * G];
__device__ float  g_m2[G * HID];

__device__ __forceinline__ unsigned to_tf32(float x) {
    unsigned r;
    asm("cvt.rna.tf32.f32 %0, %1;" : "=r"(r) : "f"(x));
    return r;
}

// ---------------- setup ----------------
__global__ void k_setup(const float* __restrict__ w1, const float* __restrict__ b1,
                        const float* __restrict__ w2, const float* __restrict__ b2,
                        float* __restrict__ temb,
                        int* __restrict__ cnt, int* __restrict__ cur,
                        float* __restrict__ pool, int* __restrict__ gc, int* __restrict__ total,
                        int Np, int NpPad, int Nl, int NT) {
    int t = threadIdx.x;
    if (blockIdx.x == 0) {
        if (t == 0) total[0] = 0;
        __shared__ float u[128];
        if (t < 128) {
            float s = b1[t];
            #pragma unroll
            for (int k = 16; k < 32; k++) s += w1[t * 32 + k];
            u[t] = s / (1.f + expf(-s));
        }
        __syncthreads();
        if (t < 128) {
            float o = b2[t];
            #pragma unroll 8
            for (int i = 0; i < 128; i++) o += u[i] * w2[t * 128 + i];
            temb[t] = o;
        }
        return;
    }
    int i = (blockIdx.x - 1) * 256 + t;
    if (i < NT) {
        bool valid = (i < Np) || (i >= NpPad && (i - NpPad) < Nl);
        cnt[i] = valid ? 1 : 0;   // slot 0 reserved for self-loop
        cur[i] = valid ? 1 : 0;
    }
    if (i < 2 * G * HID) pool[i] = 0.f;
    if (i < 2 * G) gc[i] = 0;
}

// ---------------- CSR: count ----------------
__global__ void k_count(const int* __restrict__ pdst, const int* __restrict__ ldst,
                        int* cnt, int Ep, int El, int NpPad) {
    int i = blockIdx.x * blockDim.x + threadIdx.x;
    if (i < Ep) atomicAdd(&cnt[pdst[i]], 1);
    else if (i < Ep + El) atomicAdd(&cnt[ldst[i - Ep] + NpPad], 1);
}

// ---------------- CSR: parallel segment allocation ----------------
__global__ void k_alloc(const int* __restrict__ cnt, int* __restrict__ indptr,
                        int* __restrict__ csr, int* __restrict__ total,
                        int Np, int NpPad, int Nl, int NT) {
    int t = threadIdx.x;
    int i = blockIdx.x * 256 + t;
    int lane = t & 31, w = t >> 5;
    bool inr = (i < NT);
    bool valid = inr && ((i < Np) || (i >= NpPad && (i - NpPad) < Nl));
    int c = inr ? cnt[i] : 0;
    int v = c;
    #pragma unroll
    for (int off = 1; off < 32; off <<= 1) {
        int u = __shfl_up_sync(0xffffffff, v, off);
        if (lane >= off) v += u;
    }
    __shared__ int wt[8];
    __shared__ int sbase;
    if (lane == 31) wt[w] = v;
    __syncthreads();
    if (t < 8) {
        int x = wt[t];
        #pragma unroll
        for (int off = 1; off < 8; off <<= 1) {
            int u = __shfl_up_sync(0xff, x, off);
            if (t >= off) x += u;
        }
        wt[t] = x;
        if (t == 7) sbase = atomicAdd(total, x);
    }
    __syncthreads();
    int excl = sbase + (v - c) + (w ? wt[w - 1] : 0);
    if (inr) {
        indptr[i] = excl;
        if (valid) csr[excl] = i;   // self-loop at slot 0
    }
}

// ---------------- CSR: edge fill ----------------
__global__ void k_fill(const int* __restrict__ psrc, const int* __restrict__ pdst,
                       const int* __restrict__ lsrc, const int* __restrict__ ldst,
                       const int* __restrict__ indptr, int* cur, int* __restrict__ csr,
                       int Ep, int El, int NpPad) {
    int i = blockIdx.x * blockDim.x + threadIdx.x;
    if (i < Ep) {
        int d = pdst[i];
        int p = indptr[d] + atomicAdd(&cur[d], 1);
        csr[p] = psrc[i];
    } else if (i < Ep + El) {
        int e = i - Ep;
        int d = ldst[e] + NpPad;
        int p = indptr[d] + atomicAdd(&cur[d], 1);
        csr[p] = lsrc[e] + NpPad;
    }
}

// ---------------- encoder ----------------
__global__ void k_encode(const float* __restrict__ px, const float* __restrict__ lx,
                         const float* __restrict__ pew, const float* __restrict__ peb,
                         const float* __restrict__ lew, const float* __restrict__ leb,
                         const float* __restrict__ temb, float* __restrict__ h,
                         int Np, int NpPad, int Nl, int nbP) {
    __shared__ float sw[128 * 16];
    __shared__ float sb[128];
    __shared__ float sx[32 * 16];
    int t = threadIdx.x;
    int blk = blockIdx.x;
    const float* x; const float* ew; const float* ebp;
    int n0, Nv, base;
    if (blk < nbP) { x = px; ew = pew; ebp = peb; n0 = blk * 32; Nv = Np; base = 0; }
    else { x = lx; ew = lew; ebp = leb; n0 = NpPad + (blk - nbP) * 32; Nv = Nl; base = NpPad; }
    for (int i = t; i < 2048; i += 256) sw[i] = ew[i];
    if (t < 128) sb[t] = ebp[t] + temb[t];
    for (int i = t; i < 512; i += 256) {
        int m = i >> 4;
        int loc = n0 - base + m;
        sx[i] = (loc < Nv) ? x[loc * 16 + (i & 15)] : 0.f;
    }
    __syncthreads();
    for (int idx = t; idx < 32 * 128; idx += 256) {
        int m = idx >> 7, j = idx & 127;
        float s = sb[j];
        #pragma unroll
        for (int k = 0; k < 16; k++) s += sx[m * 16 + k] * sw[j * 16 + k];
        h[(n0 + m) * 128 + j] = s;
    }
}

// ---------------- tf32 tensor-core GEMM 64x128 + fused attn coefs, fp16 xp out ----
__global__ void __launch_bounds__(256) k_gemm_attn(
        const float* __restrict__ h,
        const float* __restrict__ Wp, const float* __restrict__ Wl,
        const float* __restrict__ asp, const float* __restrict__ adp,
        const float* __restrict__ asl, const float* __restrict__ adl,
        __half* __restrict__ xph, float* __restrict__ asn, float* __restrict__ adn,
        int NpPad, int nbP) {
    __shared__ unsigned sH[64][36];
    __shared__ unsigned sW[128][36];
    int t = threadIdx.x;
    int blk = blockIdx.x;
    const float* W; const float* As; const float* Ad;
    int n0;
    if (blk < nbP) { W = Wp; As = asp; Ad = adp; n0 = blk * 64; }
    else { W = Wl; As = asl; Ad = adl; n0 = NpPad + (blk - nbP) * 64; }

    int wid = t >> 5;
    int lane = t & 31;
    int warp_m = wid >> 1;
    int warp_n = wid & 1;
    int quad = lane >> 2;
    int lane4 = lane & 3;

    float acc[8][4];
    #pragma unroll
    for (int i = 0; i < 8; i++)
        #pragma unroll
        for (int j = 0; j < 4; j++) acc[i][j] = 0.f;

    for (int kk = 0; kk < 128; kk += 32) {
        for (int i = t; i < 1024; i += 256) {
            int j = i >> 3, kq = (i & 7) * 4;
            float4 wv = *(const float4*)&W[j * 128 + kk + kq];
            uint4 cv = make_uint4(to_tf32(wv.x), to_tf32(wv.y), to_tf32(wv.z), to_tf32(wv.w));
            *(uint4*)&sW[j][kq] = cv;
        }
        for (int i = t; i < 512; i += 256) {
            int m = i >> 3, kq = (i & 7) * 4;
            float4 hv = *(const float4*)&h[(n0 + m) * 128 + kk + kq];
            uint4 cv = make_uint4(to_tf32(hv.x), to_tf32(hv.y), to_tf32(hv.z), to_tf32(hv.w));
            *(uint4*)&sH[m][kq] = cv;
        }
        __syncthreads();
        #pragma unroll
        for (int ks = 0; ks < 4; ks++) {
            int kc = ks * 8 + lane4;
            int row = warp_m * 16 + quad;
            unsigned a0 = sH[row][kc];
            unsigned a1 = sH[row + 8][kc];
            unsigned a2 = sH[row][kc + 4];
            unsigned a3 = sH[row + 8][kc + 4];
            #pragma unroll
            for (int nt = 0; nt < 8; nt++) {
                int ncol = warp_n * 64 + nt * 8 + quad;
                unsigned b0 = sW[ncol][kc];
                unsigned b1 = sW[ncol][kc + 4];
                asm volatile(
                    "mma.sync.aligned.m16n8k8.row.col.f32.tf32.tf32.f32 "
                    "{%0,%1,%2,%3}, {%4,%5,%6,%7}, {%8,%9}, {%0,%1,%2,%3};"
                    : "+f"(acc[nt][0]), "+f"(acc[nt][1]), "+f"(acc[nt][2]), "+f"(acc[nt][3])
                    : "r"(a0), "r"(a1), "r"(a2), "r"(a3), "r"(b0), "r"(b1));
            }
        }
        __syncthreads();
    }

    int r0g = n0 + warp_m * 16 + quad;
    int r1g = r0g + 8;
    int cbase = warp_n * 64;
    float ps0h0 = 0.f, ps0h1 = 0.f, ps1h0 = 0.f, ps1h1 = 0.f;
    float pd0h0 = 0.f, pd0h1 = 0.f, pd1h0 = 0.f, pd1h1 = 0.f;
    #pragma unroll
    for (int nt = 0; nt < 8; nt++) {
        int col = cbase + nt * 8 + lane4 * 2;
        float2 as2 = *(const float2*)&As[col];
        float2 ad2 = *(const float2*)&Ad[col];
        *(__half2*)&xph[(size_t)r0g * 128 + col] = __floats2half2_rn(acc[nt][0], acc[nt][1]);
        *(__half2*)&xph[(size_t)r1g * 128 + col] = __floats2half2_rn(acc[nt][2], acc[nt][3]);
        float p0 = acc[nt][0] * as2.x + acc[nt][1] * as2.y;
        float p1 = acc[nt][2] * as2.x + acc[nt][3] * as2.y;
        float q0 = acc[nt][0] * ad2.x + acc[nt][1] * ad2.y;
        float q1 = acc[nt][2] * ad2.x + acc[nt][3] * ad2.y;
        if (nt < 4) { ps0h0 += p0; ps1h0 += p1; pd0h0 += q0; pd1h0 += q1; }
        else        { ps0h1 += p0; ps1h1 += p1; pd0h1 += q0; pd1h1 += q1; }
    }
    #pragma unroll
    for (int off = 1; off <= 2; off <<= 1) {
        ps0h0 += __shfl_xor_sync(0xffffffff, ps0h0, off);
        ps0h1 += __shfl_xor_sync(0xffffffff, ps0h1, off);
        ps1h0 += __shfl_xor_sync(0xffffffff, ps1h0, off);
        ps1h1 += __shfl_xor_sync(0xffffffff, ps1h1, off);
        pd0h0 += __shfl_xor_sync(0xffffffff, pd0h0, off);
        pd0h1 += __shfl_xor_sync(0xffffffff, pd0h1, off);
        pd1h0 += __shfl_xor_sync(0xffffffff, pd1h0, off);
        pd1h1 += __shfl_xor_sync(0xffffffff, pd1h1, off);
    }
    if (lane4 == 0) {
        int h0 = warp_n * 2, h1 = h0 + 1;
        asn[r0g * 4 + h0] = ps0h0; asn[r0g * 4 + h1] = ps0h1;
        asn[r1g * 4 + h0] = ps1h0; asn[r1g * 4 + h1] = ps1h1;
        adn[r0g * 4 + h0] = pd0h0; adn[r0g * 4 + h1] = pd0h1;
        adn[r1g * 4 + h0] = pd1h0; adn[r1g * 4 + h1] = pd1h1;
    }
}

// ---------------- aggregation: warp-per-node online softmax, fp16 gather ----------
__global__ void k_aggr(const __half* __restrict__ xph, const float* __restrict__ asn,
                       const float* __restrict__ adn,
                       const float* __restrict__ biasP, const float* __restrict__ biasL,
                       const int* __restrict__ indptr, const int* __restrict__ cnt,
                       const int* __restrict__ csr,
                       float* __restrict__ hout, int Np, int NpPad, int Nl) {
    int n = (blockIdx.x * blockDim.x + threadIdx.x) >> 5;
    int lane = threadIdx.x & 31;
    const float* bias;
    if (n < NpPad) { if (n >= Np) return; bias = biasP; }
    else { if (n - NpPad >= Nl) return; bias = biasL; }
    int hd = lane >> 3;
    int j = lane * 4;
    int base = indptr[n];
    int deg = cnt[n];
    float adn_n = adn[n * 4 + hd];
    float mymax = -1e30f, denom = 0.f;
    float4 acc = make_float4(0.f, 0.f, 0.f, 0.f);
    // 2-deep pipeline; each lane loads 8 B (4 halves)
    uint2 xv0, xv1; float av0 = 0.f, av1 = 0.f;
    {
        int s0 = csr[base];
        xv0 = *(const uint2*)(xph + (size_t)s0 * 128 + j);
        av0 = asn[s0 * 4 + hd];
    }
    if (deg > 1) {
        int s1 = csr[base + 1];
        xv1 = *(const uint2*)(xph + (size_t)s1 * 128 + j);
        av1 = asn[s1 * 4 + hd];
    }
    for (int i = 0; i < deg; i++) {
        uint2 xv2; float av2;
        if (i + 2 < deg) {
            int s2 = csr[base + i + 2];
            xv2 = *(const uint2*)(xph + (size_t)s2 * 128 + j);
            av2 = asn[s2 * 4 + hd];
        }
        float e = av0 + adn_n;
        e = (e >= 0.f) ? e : 0.2f * e;                 // leaky_relu 0.2
        float nm = fmaxf(mymax, e);
        float corr = __expf(mymax - nm);               // 0 on first edge
        float w = __expf(e - nm);
        float2 lo = __half22float2(*(__half2*)&xv0.x);
        float2 hi = __half22float2(*(__half2*)&xv0.y);
        denom = denom * corr + w;
        acc.x = acc.x * corr + w * lo.x;
        acc.y = acc.y * corr + w * lo.y;
        acc.z = acc.z * corr + w * hi.x;
        acc.w = acc.w * corr + w * hi.y;
        mymax = nm;
        xv0 = xv1; av0 = av1;
        xv1 = xv2; av1 = av2;
    }
    float inv = 1.f / (denom + 1e-16f);
    float4 o;
    o.x = fmaxf(acc.x * inv + bias[j + 0], 0.f);
    o.y = fmaxf(acc.y * inv + bias[j + 1], 0.f);
    o.z = fmaxf(acc.z * inv + bias[j + 2], 0.f);
    o.w = fmaxf(acc.w * inv + bias[j + 3], 0.f);
    *(float4*)&hout[n * 128 + j] = o;
}

// ---------------- pooling ----------------
__global__ void k_pool(const float* __restrict__ h, const int* __restrict__ pb,
                       const int* __restrict__ lb, float* pool, int* gc,
                       int Np, int NpPad, int Nl) {
    int j = threadIdx.x;  // 128
    int n0 = blockIdx.x * 64;
    int nend = n0 + 64;
    int curg = -1;
    float acc = 0.f;
    int cacc = 0;
    for (int n = n0; n < nend; n++) {
        int g;
        if (n < Np) g = pb[n];
        else if (n >= NpPad && (n - NpPad) < Nl) g = G + lb[n - NpPad];
        else continue;
        if (g != curg) {
            if (curg >= 0) {
                atomicAdd(&pool[curg * HID + j], acc);
                if (j == 0) atomicAdd(&gc[curg], cacc);
            }
            curg = g; acc = 0.f; cacc = 0;
        }
        acc += h[n * HID + j];
        cacc++;
    }
    if (curg >= 0) {
        atomicAdd(&pool[curg * HID + j], acc);
        if (j == 0) atomicAdd(&gc[curg], cacc);
    }
}

// ---------------- prediction MLP: layers 1+2 fused per group ----------------
__global__ void k_mlp12(const float* __restrict__ pool, const int* __restrict__ gc,
                        const float* __restrict__ w1, const float* __restrict__ b1,
                        const float* __restrict__ w2, const float* __restrict__ b2,
                        float* __restrict__ out2) {
    int g = blockIdx.x, o = threadIdx.x;  // 256 threads
    __shared__ float jv[256];
    __shared__ float h1[256];
    if (o < 128) {
        float c = fmaxf((float)gc[g], 1.f);
        jv[o] = pool[g * HID + o] / c;
    } else {
        float c = fmaxf((float)gc[G + g], 1.f);
        jv[o] = pool[(G + g) * HID + (o - 128)] / c;
    }
    __syncthreads();
    float s = b1[o];
    #pragma unroll 8
    for (int c2 = 0; c2 < 256; c2++) s += jv[c2] * w1[o * 256 + c2];
    h1[o] = fmaxf(s, 0.f);
    __syncthreads();
    if (o < 128) {
        float s2 = b2[o];
        #pragma unroll 8
        for (int c2 = 0; c2 < 256; c2++) s2 += h1[c2] * w2[o * 256 + c2];
        out2[g * 128 + o] = fmaxf(s2, 0.f);
    }
}
__global__ void k_mlp3(const float* __restrict__ in, const float* __restrict__ w,
                       const float* __restrict__ b, float* __restrict__ out) {
    int g = threadIdx.x;
    if (g < G) {
        float s = b[0];
        #pragma unroll 8
        for (int c = 0; c < 128; c++) s += in[g * 128 + c] * w[c];
        out[g] = s;
    }
}

// ---------------- launch ----------------
extern "C" void kernel_launch(void* const* d_in, const int* in_sizes, int n_in,
                              void* d_out, int out_size) {
    const float* px  = (const float*)d_in[0];
    const int*   pei = (const int*)d_in[1];
    const int*   pb  = (const int*)d_in[2];
    const float* lx  = (const float*)d_in[3];
    const int*   lei = (const int*)d_in[4];
    const int*   lb  = (const int*)d_in[5];
    const float* tw1 = (const float*)d_in[6];
    const float* tb1 = (const float*)d_in[7];
    const float* tw2 = (const float*)d_in[8];
    const float* tb2 = (const float*)d_in[9];
    const float* pew = (const float*)d_in[10];
    const float* peb = (const float*)d_in[11];
    const float* lew = (const float*)d_in[12];
    const float* leb = (const float*)d_in[13];
    const float* pgW = (const float*)d_in[14];
    const float* pgs = (const float*)d_in[15];
    const float* pgd = (const float*)d_in[16];
    const float* pgb = (const float*)d_in[17];
    const float* lgW = (const float*)d_in[18];
    const float* lgs = (const float*)d_in[19];
    const float* lgd = (const float*)d_in[20];
    const float* lgb = (const float*)d_in[21];
    const float* prw1 = (const float*)d_in[22];
    const float* prb1 = (const float*)d_in[23];
    const float* prw2 = (const float*)d_in[24];
    const float* prb2 = (const float*)d_in[25];
    const float* prw3 = (const float*)d_in[26];
    const float* prb3 = (const float*)d_in[27];

    int Np = in_sizes[0] / 16, Ep = in_sizes[1] / 2;
    int Nl = in_sizes[3] / 16, El = in_sizes[4] / 2;
    int NpPad = (Np + 63) / 64 * 64;
    int NT = NpPad + (Nl + 63) / 64 * 64;
    int Etot = Ep + El;

    float *h0, *h1, *asn, *adn, *temb, *pool, *m2;
    __half *xph;
    int *cnt, *cur, *indptr, *csr, *gc, *total;
    cudaGetSymbolAddress((void**)&h0, g_h0);
    cudaGetSymbolAddress((void**)&h1, g_h1);
    cudaGetSymbolAddress((void**)&xph, g_xph);
    cudaGetSymbolAddress((void**)&asn, g_asn);
    cudaGetSymbolAddress((void**)&adn, g_adn);
    cudaGetSymbolAddress((void**)&temb, g_temb);
    cudaGetSymbolAddress((void**)&pool, g_pool);
    cudaGetSymbolAddress((void**)&m2, g_m2);
    cudaGetSymbolAddress((void**)&cnt, g_cnt);
    cudaGetSymbolAddress((void**)&cur, g_cur);
    cudaGetSymbolAddress((void**)&indptr, g_indptr);
    cudaGetSymbolAddress((void**)&csr, g_csr);
    cudaGetSymbolAddress((void**)&gc, g_gcnt);
    cudaGetSymbolAddress((void**)&total, g_total);

    const int* pdst = pei + Ep;
    const int* ldst = lei + El;

    int setup_work = NT > 2 * G * HID ? NT : 2 * G * HID;
    k_setup<<<1 + (setup_work + 255) / 256, 256>>>(tw1, tb1, tw2, tb2, temb,
                                                   cnt, cur, pool, gc, total,
                                                   Np, NpPad, Nl, NT);
    k_count<<<(Etot + 255) / 256, 256>>>(pdst, ldst, cnt, Ep, El, NpPad);
    k_alloc<<<(NT + 255) / 256, 256>>>(cnt, indptr, csr, total, Np, NpPad, Nl, NT);
    k_fill<<<(Etot + 255) / 256, 256>>>(pei, pdst, lei, ldst, indptr, cur, csr,
                                        Ep, El, NpPad);
    int nbP32 = NpPad / 32, nbL32 = (Nl + 31) / 32;
    k_encode<<<nbP32 + nbL32, 256>>>(px, lx, pew, peb, lew, leb, temb, h0,
                                     Np, NpPad, Nl, nbP32);

    int nbP64 = NpPad / 64, nbL64 = (Nl + 63) / 64;
    int nAggr = NpPad + Nl;
    int aggrBlocks = (nAggr * 32 + 255) / 256;
    float* hin = h0;
    float* hout = h1;
    for (int l = 0; l < DEPTH; l++) {
        k_gemm_attn<<<nbP64 + nbL64, 256>>>(hin,
            pgW + l * HID * HID, lgW + l * HID * HID,
            pgs + l * HID, pgd + l * HID, lgs + l * HID, lgd + l * HID,
            xph, asn, adn, NpPad, nbP64);
        k_aggr<<<aggrBlocks, 256>>>(xph, asn, adn, pgb + l * HID, lgb + l * HID,
                                    indptr, cnt, csr, hout, Np, NpPad, Nl);
        float* tmp = hin; hin = hout; hout = tmp;
    }

    k_pool<<<(NT + 63) / 64, 128>>>(hin, pb, lb, pool, gc, Np, NpPad, Nl);

    k_mlp12<<<G, 256>>>(pool, gc, prw1, prb1, prw2, prb2, m2);
    k_mlp3<<<1, 32>>>(m2, prw3, prb3, (float*)d_out);
}

// round 9
// speedup vs baseline: 1.8765x; 1.0731x over previous
#include <cuda_runtime.h>
#include <cuda_fp16.h>
#include <math.h>

#define HID 128
#define G 32
#define DEPTH 4
#define N_MAX 46080
#define E_MAX 640000

// ---------------- scratch ----------------
__device__ float  g_h0[N_MAX * HID];
__device__ float  g_h1[N_MAX * HID];
__device__ __half g_xph[N_MAX * HID];
__device__ float  g_asn[N_MAX * 4];
__device__ float  g_adn[N_MAX * 4];
__device__ int    g_cnt[N_MAX];
__device__ int    g_cur[N_MAX];
__device__ int    g_indptr[N_MAX];
__device__ int    g_csr[E_MAX];
__device__ int    g_total[1];
__device__ float  g_temb[HID];
__device__ float  g_pool[2 * G * HID];
__device__ int    g_gcnt[2 * G];
__device__ float  g_m2[G * HID];

__device__ __forceinline__ unsigned to_tf32(float x) {
    unsigned r;
    asm("cvt.rna.tf32.f32 %0, %1;" : "=r"(r) : "f"(x));
    return r;
}

// ---------------- setup ----------------
__global__ void k_setup(const float* __restrict__ w1, const float* __restrict__ b1,
                        const float* __restrict__ w2, const float* __restrict__ b2,
                        float* __restrict__ temb,
                        int* __restrict__ cnt, int* __restrict__ cur,
                        float* __restrict__ pool, int* __restrict__ gc, int* __restrict__ total,
                        int Np, int NpPad, int Nl, int NT) {
    int t = threadIdx.x;
    if (blockIdx.x == 0) {
        if (t == 0) total[0] = 0;
        __shared__ float u[128];
        if (t < 128) {
            float s = b1[t];
            #pragma unroll
            for (int k = 16; k < 32; k++) s += w1[t * 32 + k];
            u[t] = s / (1.f + expf(-s));
        }
        __syncthreads();
        if (t < 128) {
            float o = b2[t];
            #pragma unroll 8
            for (int i = 0; i < 128; i++) o += u[i] * w2[t * 128 + i];
            temb[t] = o;
        }
        return;
    }
    int i = (blockIdx.x - 1) * 256 + t;
    if (i < NT) {
        bool valid = (i < Np) || (i >= NpPad && (i - NpPad) < Nl);
        cnt[i] = valid ? 1 : 0;   // slot 0 reserved for self-loop
        cur[i] = valid ? 1 : 0;
    }
    if (i < 2 * G * HID) pool[i] = 0.f;
    if (i < 2 * G) gc[i] = 0;
}

// ---------------- CSR: count ----------------
__global__ void k_count(const int* __restrict__ pdst, const int* __restrict__ ldst,
                        int* cnt, int Ep, int El, int NpPad) {
    int i = blockIdx.x * blockDim.x + threadIdx.x;
    if (i < Ep) atomicAdd(&cnt[pdst[i]], 1);
    else if (i < Ep + El) atomicAdd(&cnt[ldst[i - Ep] + NpPad], 1);
}

// ---------------- CSR: parallel segment allocation ----------------
__global__ void k_alloc(const int* __restrict__ cnt, int* __restrict__ indptr,
                        int* __restrict__ csr, int* __restrict__ total,
                        int Np, int NpPad, int Nl, int NT) {
    int t = threadIdx.x;
    int i = blockIdx.x * 256 + t;
    int lane = t & 31, w = t >> 5;
    bool inr = (i < NT);
    bool valid = inr && ((i < Np) || (i >= NpPad && (i - NpPad) < Nl));
    int c = inr ? cnt[i] : 0;
    int v = c;
    #pragma unroll
    for (int off = 1; off < 32; off <<= 1) {
        int u = __shfl_up_sync(0xffffffff, v, off);
        if (lane >= off) v += u;
    }
    __shared__ int wt[8];
    __shared__ int sbase;
    if (lane == 31) wt[w] = v;
    __syncthreads();
    if (t < 8) {
        int x = wt[t];
        #pragma unroll
        for (int off = 1; off < 8; off <<= 1) {
            int u = __shfl_up_sync(0xff, x, off);
            if (t >= off) x += u;
        }
        wt[t] = x;
        if (t == 7) sbase = atomicAdd(total, x);
    }
    __syncthreads();
    int excl = sbase + (v - c) + (w ? wt[w - 1] : 0);
    if (inr) {
        indptr[i] = excl;
        if (valid) csr[excl] = i;   // self-loop at slot 0
    }
}

// ---------------- CSR: edge fill ----------------
__global__ void k_fill(const int* __restrict__ psrc, const int* __restrict__ pdst,
                       const int* __restrict__ lsrc, const int* __restrict__ ldst,
                       const int* __restrict__ indptr, int* cur, int* __restrict__ csr,
                       int Ep, int El, int NpPad) {
    int i = blockIdx.x * blockDim.x + threadIdx.x;
    if (i < Ep) {
        int d = pdst[i];
        int p = indptr[d] + atomicAdd(&cur[d], 1);
        csr[p] = psrc[i];
    } else if (i < Ep + El) {
        int e = i - Ep;
        int d = ldst[e] + NpPad;
        int p = indptr[d] + atomicAdd(&cur[d], 1);
        csr[p] = lsrc[e] + NpPad;
    }
}

// ---------------- encoder ----------------
__global__ void k_encode(const float* __restrict__ px, const float* __restrict__ lx,
                         const float* __restrict__ pew, const float* __restrict__ peb,
                         const float* __restrict__ lew, const float* __restrict__ leb,
                         const float* __restrict__ temb, float* __restrict__ h,
                         int Np, int NpPad, int Nl, int nbP) {
    __shared__ float sw[128 * 16];
    __shared__ float sb[128];
    __shared__ float sx[32 * 16];
    int t = threadIdx.x;
    int blk = blockIdx.x;
    const float* x; const float* ew; const float* ebp;
    int n0, Nv, base;
    if (blk < nbP) { x = px; ew = pew; ebp = peb; n0 = blk * 32; Nv = Np; base = 0; }
    else { x = lx; ew = lew; ebp = leb; n0 = NpPad + (blk - nbP) * 32; Nv = Nl; base = NpPad; }
    for (int i = t; i < 2048; i += 256) sw[i] = ew[i];
    if (t < 128) sb[t] = ebp[t] + temb[t];
    for (int i = t; i < 512; i += 256) {
        int m = i >> 4;
        int loc = n0 - base + m;
        sx[i] = (loc < Nv) ? x[loc * 16 + (i & 15)] : 0.f;
    }
    __syncthreads();
    for (int idx = t; idx < 32 * 128; idx += 256) {
        int m = idx >> 7, j = idx & 127;
        float s = sb[j];
        #pragma unroll
        for (int k = 0; k < 16; k++) s += sx[m * 16 + k] * sw[j * 16 + k];
        h[(n0 + m) * 128 + j] = s;
    }
}

// ---------------- tf32 tensor-core GEMM 64x128 + fused attn coefs, fp16 xp out ----
__global__ void __launch_bounds__(256) k_gemm_attn(
        const float* __restrict__ h,
        const float* __restrict__ Wp, const float* __restrict__ Wl,
        const float* __restrict__ asp, const float* __restrict__ adp,
        const float* __restrict__ asl, const float* __restrict__ adl,
        __half* __restrict__ xph, float* __restrict__ asn, float* __restrict__ adn,
        int NpPad, int nbP) {
    __shared__ unsigned sH[64][36];
    __shared__ unsigned sW[128][36];
    int t = threadIdx.x;
    int blk = blockIdx.x;
    const float* W; const float* As; const float* Ad;
    int n0;
    if (blk < nbP) { W = Wp; As = asp; Ad = adp; n0 = blk * 64; }
    else { W = Wl; As = asl; Ad = adl; n0 = NpPad + (blk - nbP) * 64; }

    int wid = t >> 5;
    int lane = t & 31;
    int warp_m = wid >> 1;
    int warp_n = wid & 1;
    int quad = lane >> 2;
    int lane4 = lane & 3;

    float acc[8][4];
    #pragma unroll
    for (int i = 0; i < 8; i++)
        #pragma unroll
        for (int j = 0; j < 4; j++) acc[i][j] = 0.f;

    for (int kk = 0; kk < 128; kk += 32) {
        for (int i = t; i < 1024; i += 256) {
            int j = i >> 3, kq = (i & 7) * 4;
            float4 wv = *(const float4*)&W[j * 128 + kk + kq];
            uint4 cv = make_uint4(to_tf32(wv.x), to_tf32(wv.y), to_tf32(wv.z), to_tf32(wv.w));
            *(uint4*)&sW[j][kq] = cv;
        }
        for (int i = t; i < 512; i += 256) {
            int m = i >> 3, kq = (i & 7) * 4;
            float4 hv = *(const float4*)&h[(n0 + m) * 128 + kk + kq];
            uint4 cv = make_uint4(to_tf32(hv.x), to_tf32(hv.y), to_tf32(hv.z), to_tf32(hv.w));
            *(uint4*)&sH[m][kq] = cv;
        }
        __syncthreads();
        #pragma unroll
        for (int ks = 0; ks < 4; ks++) {
            int kc = ks * 8 + lane4;
            int row = warp_m * 16 + quad;
            unsigned a0 = sH[row][kc];
            unsigned a1 = sH[row + 8][kc];
            unsigned a2 = sH[row][kc + 4];
            unsigned a3 = sH[row + 8][kc + 4];
            #pragma unroll
            for (int nt = 0; nt < 8; nt++) {
                int ncol = warp_n * 64 + nt * 8 + quad;
                unsigned b0 = sW[ncol][kc];
                unsigned b1 = sW[ncol][kc + 4];
                asm volatile(
                    "mma.sync.aligned.m16n8k8.row.col.f32.tf32.tf32.f32 "
                    "{%0,%1,%2,%3}, {%4,%5,%6,%7}, {%8,%9}, {%0,%1,%2,%3};"
                    : "+f"(acc[nt][0]), "+f"(acc[nt][1]), "+f"(acc[nt][2]), "+f"(acc[nt][3])
                    : "r"(a0), "r"(a1), "r"(a2), "r"(a3), "r"(b0), "r"(b1));
            }
        }
        __syncthreads();
    }

    int r0g = n0 + warp_m * 16 + quad;
    int r1g = r0g + 8;
    int cbase = warp_n * 64;
    float ps0h0 = 0.f, ps0h1 = 0.f, ps1h0 = 0.f, ps1h1 = 0.f;
    float pd0h0 = 0.f, pd0h1 = 0.f, pd1h0 = 0.f, pd1h1 = 0.f;
    #pragma unroll
    for (int nt = 0; nt < 8; nt++) {
        int col = cbase + nt * 8 + lane4 * 2;
        float2 as2 = *(const float2*)&As[col];
        float2 ad2 = *(const float2*)&Ad[col];
        *(__half2*)&xph[(size_t)r0g * 128 + col] = __floats2half2_rn(acc[nt][0], acc[nt][1]);
        *(__half2*)&xph[(size_t)r1g * 128 + col] = __floats2half2_rn(acc[nt][2], acc[nt][3]);
        float p0 = acc[nt][0] * as2.x + acc[nt][1] * as2.y;
        float p1 = acc[nt][2] * as2.x + acc[nt][3] * as2.y;
        float q0 = acc[nt][0] * ad2.x + acc[nt][1] * ad2.y;
        float q1 = acc[nt][2] * ad2.x + acc[nt][3] * ad2.y;
        if (nt < 4) { ps0h0 += p0; ps1h0 += p1; pd0h0 += q0; pd1h0 += q1; }
        else        { ps0h1 += p0; ps1h1 += p1; pd0h1 += q0; pd1h1 += q1; }
    }
    #pragma unroll
    for (int off = 1; off <= 2; off <<= 1) {
        ps0h0 += __shfl_xor_sync(0xffffffff, ps0h0, off);
        ps0h1 += __shfl_xor_sync(0xffffffff, ps0h1, off);
        ps1h0 += __shfl_xor_sync(0xffffffff, ps1h0, off);
        ps1h1 += __shfl_xor_sync(0xffffffff, ps1h1, off);
        pd0h0 += __shfl_xor_sync(0xffffffff, pd0h0, off);
        pd0h1 += __shfl_xor_sync(0xffffffff, pd0h1, off);
        pd1h0 += __shfl_xor_sync(0xffffffff, pd1h0, off);
        pd1h1 += __shfl_xor_sync(0xffffffff, pd1h1, off);
    }
    if (lane4 == 0) {
        int h0 = warp_n * 2, h1 = h0 + 1;
        asn[r0g * 4 + h0] = ps0h0; asn[r0g * 4 + h1] = ps0h1;
        asn[r1g * 4 + h0] = ps1h0; asn[r1g * 4 + h1] = ps1h1;
        adn[r0g * 4 + h0] = pd0h0; adn[r0g * 4 + h1] = pd0h1;
        adn[r1g * 4 + h0] = pd1h0; adn[r1g * 4 + h1] = pd1h1;
    }
}

// ---------------- aggregation: no-max softmax (clamped exp), fp16 gather ----------
// exp(e)/sum(exp(e)) is mathematically identical to the max-subtracted form;
// clamp at 60 prevents fp32 overflow. Removes the serial mymax/corr chain.
__global__ void k_aggr(const __half* __restrict__ xph, const float* __restrict__ asn,
                       const float* __restrict__ adn,
                       const float* __restrict__ biasP, const float* __restrict__ biasL,
                       const int* __restrict__ indptr, const int* __restrict__ cnt,
                       const int* __restrict__ csr,
                       float* __restrict__ hout, int Np, int NpPad, int Nl) {
    int n = (blockIdx.x * blockDim.x + threadIdx.x) >> 5;
    int lane = threadIdx.x & 31;
    const float* bias;
    if (n < NpPad) { if (n >= Np) return; bias = biasP; }
    else { if (n - NpPad >= Nl) return; bias = biasL; }
    int hd = lane >> 3;
    int j = lane * 4;
    int base = indptr[n];
    int deg = cnt[n];
    float adn_n = adn[n * 4 + hd];
    float denom = 0.f;
    float4 acc = make_float4(0.f, 0.f, 0.f, 0.f);
    // 2-deep pipeline; each lane loads 8 B (4 halves)
    uint2 xv0, xv1; float av0 = 0.f, av1 = 0.f;
    {
        int s0 = csr[base];
        xv0 = *(const uint2*)(xph + (size_t)s0 * 128 + j);
        av0 = asn[s0 * 4 + hd];
    }
    if (deg > 1) {
        int s1 = csr[base + 1];
        xv1 = *(const uint2*)(xph + (size_t)s1 * 128 + j);
        av1 = asn[s1 * 4 + hd];
    }
    for (int i = 0; i < deg; i++) {
        uint2 xv2; float av2;
        if (i + 2 < deg) {
            int s2 = csr[base + i + 2];
            xv2 = *(const uint2*)(xph + (size_t)s2 * 128 + j);
            av2 = asn[s2 * 4 + hd];
        }
        float e = av0 + adn_n;
        e = (e >= 0.f) ? e : 0.2f * e;                 // leaky_relu 0.2
        float w = __expf(fminf(e, 60.f));              // no-max softmax, overflow-clamped
        float2 lo = __half22float2(*(__half2*)&xv0.x);
        float2 hi = __half22float2(*(__half2*)&xv0.y);
        denom += w;
        acc.x += w * lo.x;
        acc.y += w * lo.y;
        acc.z += w * hi.x;
        acc.w += w * hi.y;
        xv0 = xv1; av0 = av1;
        xv1 = xv2; av1 = av2;
    }
    float inv = 1.f / (denom + 1e-16f);
    float4 o;
    o.x = fmaxf(acc.x * inv + bias[j + 0], 0.f);
    o.y = fmaxf(acc.y * inv + bias[j + 1], 0.f);
    o.z = fmaxf(acc.z * inv + bias[j + 2], 0.f);
    o.w = fmaxf(acc.w * inv + bias[j + 3], 0.f);
    *(float4*)&hout[n * 128 + j] = o;
}

// ---------------- pooling ----------------
__global__ void k_pool(const float* __restrict__ h, const int* __restrict__ pb,
                       const int* __restrict__ lb, float* pool, int* gc,
                       int Np, int NpPad, int Nl) {
    int j = threadIdx.x;  // 128
    int n0 = blockIdx.x * 64;
    int nend = n0 + 64;
    int curg = -1;
    float acc = 0.f;
    int cacc = 0;
    for (int n = n0; n < nend; n++) {
        int g;
        if (n < Np) g = pb[n];
        else if (n >= NpPad && (n - NpPad) < Nl) g = G + lb[n - NpPad];
        else continue;
        if (g != curg) {
            if (curg >= 0) {
                atomicAdd(&pool[curg * HID + j], acc);
                if (j == 0) atomicAdd(&gc[curg], cacc);
            }
            curg = g; acc = 0.f; cacc = 0;
        }
        acc += h[n * HID + j];
        cacc++;
    }
    if (curg >= 0) {
        atomicAdd(&pool[curg * HID + j], acc);
        if (j == 0) atomicAdd(&gc[curg], cacc);
    }
}

// ---------------- prediction MLP: layers 1+2 fused per group ----------------
__global__ void k_mlp12(const float* __restrict__ pool, const int* __restrict__ gc,
                        const float* __restrict__ w1, const float* __restrict__ b1,
                        const float* __restrict__ w2, const float* __restrict__ b2,
                        float* __restrict__ out2) {
    int g = blockIdx.x, o = threadIdx.x;  // 256 threads
    __shared__ float jv[256];
    __shared__ float h1[256];
    if (o < 128) {
        float c = fmaxf((float)gc[g], 1.f);
        jv[o] = pool[g * HID + o] / c;
    } else {
        float c = fmaxf((float)gc[G + g], 1.f);
        jv[o] = pool[(G + g) * HID + (o - 128)] / c;
    }
    __syncthreads();
    float s = b1[o];
    #pragma unroll 8
    for (int c2 = 0; c2 < 256; c2++) s += jv[c2] * w1[o * 256 + c2];
    h1[o] = fmaxf(s, 0.f);
    __syncthreads();
    if (o < 128) {
        float s2 = b2[o];
        #pragma unroll 8
        for (int c2 = 0; c2 < 256; c2++) s2 += h1[c2] * w2[o * 256 + c2];
        out2[g * 128 + o] = fmaxf(s2, 0.f);
    }
}
__global__ void k_mlp3(const float* __restrict__ in, const float* __restrict__ w,
                       const float* __restrict__ b, float* __restrict__ out) {
    int g = threadIdx.x;
    if (g < G) {
        float s = b[0];
        #pragma unroll 8
        for (int c = 0; c < 128; c++) s += in[g * 128 + c] * w[c];
        out[g] = s;
    }
}

// ---------------- launch ----------------
extern "C" void kernel_launch(void* const* d_in, const int* in_sizes, int n_in,
                              void* d_out, int out_size) {
    const float* px  = (const float*)d_in[0];
    const int*   pei = (const int*)d_in[1];
    const int*   pb  = (const int*)d_in[2];
    const float* lx  = (const float*)d_in[3];
    const int*   lei = (const int*)d_in[4];
    const int*   lb  = (const int*)d_in[5];
    const float* tw1 = (const float*)d_in[6];
    const float* tb1 = (const float*)d_in[7];
    const float* tw2 = (const float*)d_in[8];
    const float* tb2 = (const float*)d_in[9];
    const float* pew = (const float*)d_in[10];
    const float* peb = (const float*)d_in[11];
    const float* lew = (const float*)d_in[12];
    const float* leb = (const float*)d_in[13];
    const float* pgW = (const float*)d_in[14];
    const float* pgs = (const float*)d_in[15];
    const float* pgd = (const float*)d_in[16];
    const float* pgb = (const float*)d_in[17];
    const float* lgW = (const float*)d_in[18];
    const float* lgs = (const float*)d_in[19];
    const float* lgd = (const float*)d_in[20];
    const float* lgb = (const float*)d_in[21];
    const float* prw1 = (const float*)d_in[22];
    const float* prb1 = (const float*)d_in[23];
    const float* prw2 = (const float*)d_in[24];
    const float* prb2 = (const float*)d_in[25];
    const float* prw3 = (const float*)d_in[26];
    const float* prb3 = (const float*)d_in[27];

    int Np = in_sizes[0] / 16, Ep = in_sizes[1] / 2;
    int Nl = in_sizes[3] / 16, El = in_sizes[4] / 2;
    int NpPad = (Np + 63) / 64 * 64;
    int NT = NpPad + (Nl + 63) / 64 * 64;
    int Etot = Ep + El;

    float *h0, *h1, *asn, *adn, *temb, *pool, *m2;
    __half *xph;
    int *cnt, *cur, *indptr, *csr, *gc, *total;
    cudaGetSymbolAddress((void**)&h0, g_h0);
    cudaGetSymbolAddress((void**)&h1, g_h1);
    cudaGetSymbolAddress((void**)&xph, g_xph);
    cudaGetSymbolAddress((void**)&asn, g_asn);
    cudaGetSymbolAddress((void**)&adn, g_adn);
    cudaGetSymbolAddress((void**)&temb, g_temb);
    cudaGetSymbolAddress((void**)&pool, g_pool);
    cudaGetSymbolAddress((void**)&m2, g_m2);
    cudaGetSymbolAddress((void**)&cnt, g_cnt);
    cudaGetSymbolAddress((void**)&cur, g_cur);
    cudaGetSymbolAddress((void**)&indptr, g_indptr);
    cudaGetSymbolAddress((void**)&csr, g_csr);
    cudaGetSymbolAddress((void**)&gc, g_gcnt);
    cudaGetSymbolAddress((void**)&total, g_total);

    const int* pdst = pei + Ep;
    const int* ldst = lei + El;

    int setup_work = NT > 2 * G * HID ? NT : 2 * G * HID;
    k_setup<<<1 + (setup_work + 255) / 256, 256>>>(tw1, tb1, tw2, tb2, temb,
                                                   cnt, cur, pool, gc, total,
                                                   Np, NpPad, Nl, NT);
    k_count<<<(Etot + 255) / 256, 256>>>(pdst, ldst, cnt, Ep, El, NpPad);
    k_alloc<<<(NT + 255) / 256, 256>>>(cnt, indptr, csr, total, Np, NpPad, Nl, NT);
    k_fill<<<(Etot + 255) / 256, 256>>>(pei, pdst, lei, ldst, indptr, cur, csr,
                                        Ep, El, NpPad);
    int nbP32 = NpPad / 32, nbL32 = (Nl + 31) / 32;
    k_encode<<<nbP32 + nbL32, 256>>>(px, lx, pew, peb, lew, leb, temb, h0,
                                     Np, NpPad, Nl, nbP32);

    int nbP64 = NpPad / 64, nbL64 = (Nl + 63) / 64;
    int nAggr = NpPad + Nl;
    int aggrBlocks = (nAggr * 32 + 255) / 256;
    float* hin = h0;
    float* hout = h1;
    for (int l = 0; l < DEPTH; l++) {
        k_gemm_attn<<<nbP64 + nbL64, 256>>>(hin,
            pgW + l * HID * HID, lgW + l * HID * HID,
            pgs + l * HID, pgd + l * HID, lgs + l * HID, lgd + l * HID,
            xph, asn, adn, NpPad, nbP64);
        k_aggr<<<aggrBlocks, 256>>>(xph, asn, adn, pgb + l * HID, lgb + l * HID,
                                    indptr, cnt, csr, hout, Np, NpPad, Nl);
        float* tmp = hin; hin = hout; hout = tmp;
    }

    k_pool<<<(NT + 63) / 64, 128>>>(hin, pb, lb, pool, gc, Np, NpPad, Nl);

    k_mlp12<<<G, 256>>>(pool, gc, prw1, prb1, prw2, prb2, m2);
    k_mlp3<<<1, 32>>>(m2, prw3, prb3, (float*)d_out);
}

// round 10
// speedup vs baseline: 1.8940x; 1.0093x over previous
#include <cuda_runtime.h>
#include <cuda_fp16.h>
#include <math.h>

#define HID 128
#define G 32
#define DEPTH 4
#define N_MAX 46080
#define E_MAX 640000

// ---------------- scratch ----------------
__device__ float  g_h0[N_MAX * HID];
__device__ float  g_h1[N_MAX * HID];
__device__ __half g_xph[N_MAX * HID];
__device__ float  g_asn[N_MAX * 4];
__device__ float  g_adn[N_MAX * 4];
__device__ int    g_cnt[N_MAX];
__device__ int    g_cur[N_MAX];
__device__ int    g_indptr[N_MAX];
__device__ int    g_csr[E_MAX];
__device__ int    g_total[1];
__device__ float  g_temb[HID];
__device__ float  g_pool[2 * G * HID];
__device__ int    g_gcnt[2 * G];
__device__ float  g_m2[G * HID];

__device__ __forceinline__ unsigned to_tf32(float x) {
    unsigned r;
    asm("cvt.rna.tf32.f32 %0, %1;" : "=r"(r) : "f"(x));
    return r;
}

// ---------------- setup ----------------
__global__ void k_setup(const float* __restrict__ w1, const float* __restrict__ b1,
                        const float* __restrict__ w2, const float* __restrict__ b2,
                        float* __restrict__ temb,
                        int* __restrict__ cnt, int* __restrict__ cur,
                        float* __restrict__ pool, int* __restrict__ gc, int* __restrict__ total,
                        int Np, int NpPad, int Nl, int NT) {
    int t = threadIdx.x;
    if (blockIdx.x == 0) {
        if (t == 0) total[0] = 0;
        __shared__ float u[128];
        if (t < 128) {
            float s = b1[t];
            #pragma unroll
            for (int k = 16; k < 32; k++) s += w1[t * 32 + k];
            u[t] = s / (1.f + expf(-s));
        }
        __syncthreads();
        if (t < 128) {
            float o = b2[t];
            #pragma unroll 8
            for (int i = 0; i < 128; i++) o += u[i] * w2[t * 128 + i];
            temb[t] = o;
        }
        return;
    }
    int i = (blockIdx.x - 1) * 256 + t;
    if (i < NT) {
        bool valid = (i < Np) || (i >= NpPad && (i - NpPad) < Nl);
        cnt[i] = valid ? 1 : 0;   // slot 0 reserved for self-loop
        cur[i] = valid ? 1 : 0;
    }
    if (i < 2 * G * HID) pool[i] = 0.f;
    if (i < 2 * G) gc[i] = 0;
}

// ---------------- CSR: count ----------------
__global__ void k_count(const int* __restrict__ pdst, const int* __restrict__ ldst,
                        int* cnt, int Ep, int El, int NpPad) {
    int i = blockIdx.x * blockDim.x + threadIdx.x;
    if (i < Ep) atomicAdd(&cnt[pdst[i]], 1);
    else if (i < Ep + El) atomicAdd(&cnt[ldst[i - Ep] + NpPad], 1);
}

// ---------------- CSR: parallel segment allocation ----------------
__global__ void k_alloc(const int* __restrict__ cnt, int* __restrict__ indptr,
                        int* __restrict__ csr, int* __restrict__ total,
                        int Np, int NpPad, int Nl, int NT) {
    int t = threadIdx.x;
    int i = blockIdx.x * 256 + t;
    int lane = t & 31, w = t >> 5;
    bool inr = (i < NT);
    bool valid = inr && ((i < Np) || (i >= NpPad && (i - NpPad) < Nl));
    int c = inr ? cnt[i] : 0;
    int v = c;
    #pragma unroll
    for (int off = 1; off < 32; off <<= 1) {
        int u = __shfl_up_sync(0xffffffff, v, off);
        if (lane >= off) v += u;
    }
    __shared__ int wt[8];
    __shared__ int sbase;
    if (lane == 31) wt[w] = v;
    __syncthreads();
    if (t < 8) {
        int x = wt[t];
        #pragma unroll
        for (int off = 1; off < 8; off <<= 1) {
            int u = __shfl_up_sync(0xff, x, off);
            if (t >= off) x += u;
        }
        wt[t] = x;
        if (t == 7) sbase = atomicAdd(total, x);
    }
    __syncthreads();
    int excl = sbase + (v - c) + (w ? wt[w - 1] : 0);
    if (inr) {
        indptr[i] = excl;
        if (valid) csr[excl] = i;   // self-loop at slot 0
    }
}

// ---------------- CSR: edge fill ----------------
__global__ void k_fill(const int* __restrict__ psrc, const int* __restrict__ pdst,
                       const int* __restrict__ lsrc, const int* __restrict__ ldst,
                       const int* __restrict__ indptr, int* cur, int* __restrict__ csr,
                       int Ep, int El, int NpPad) {
    int i = blockIdx.x * blockDim.x + threadIdx.x;
    if (i < Ep) {
        int d = pdst[i];
        int p = indptr[d] + atomicAdd(&cur[d], 1);
        csr[p] = psrc[i];
    } else if (i < Ep + El) {
        int e = i - Ep;
        int d = ldst[e] + NpPad;
        int p = indptr[d] + atomicAdd(&cur[d], 1);
        csr[p] = lsrc[e] + NpPad;
    }
}

// ---------------- encoder ----------------
__global__ void k_encode(const float* __restrict__ px, const float* __restrict__ lx,
                         const float* __restrict__ pew, const float* __restrict__ peb,
                         const float* __restrict__ lew, const float* __restrict__ leb,
                         const float* __restrict__ temb, float* __restrict__ h,
                         int Np, int NpPad, int Nl, int nbP) {
    __shared__ float sw[128 * 16];
    __shared__ float sb[128];
    __shared__ float sx[32 * 16];
    int t = threadIdx.x;
    int blk = blockIdx.x;
    const float* x; const float* ew; const float* ebp;
    int n0, Nv, base;
    if (blk < nbP) { x = px; ew = pew; ebp = peb; n0 = blk * 32; Nv = Np; base = 0; }
    else { x = lx; ew = lew; ebp = leb; n0 = NpPad + (blk - nbP) * 32; Nv = Nl; base = NpPad; }
    for (int i = t; i < 2048; i += 256) sw[i] = ew[i];
    if (t < 128) sb[t] = ebp[t] + temb[t];
    for (int i = t; i < 512; i += 256) {
        int m = i >> 4;
        int loc = n0 - base + m;
        sx[i] = (loc < Nv) ? x[loc * 16 + (i & 15)] : 0.f;
    }
    __syncthreads();
    for (int idx = t; idx < 32 * 128; idx += 256) {
        int m = idx >> 7, j = idx & 127;
        float s = sb[j];
        #pragma unroll
        for (int k = 0; k < 16; k++) s += sx[m * 16 + k] * sw[j * 16 + k];
        h[(n0 + m) * 128 + j] = s;
    }
}

// ---------------- tf32 tensor-core GEMM 64x128 + fused attn coefs, fp16 xp out ----
__global__ void __launch_bounds__(256) k_gemm_attn(
        const float* __restrict__ h,
        const float* __restrict__ Wp, const float* __restrict__ Wl,
        const float* __restrict__ asp, const float* __restrict__ adp,
        const float* __restrict__ asl, const float* __restrict__ adl,
        __half* __restrict__ xph, float* __restrict__ asn, float* __restrict__ adn,
        int NpPad, int nbP) {
    __shared__ unsigned sH[64][36];
    __shared__ unsigned sW[128][36];
    int t = threadIdx.x;
    int blk = blockIdx.x;
    const float* W; const float* As; const float* Ad;
    int n0;
    if (blk < nbP) { W = Wp; As = asp; Ad = adp; n0 = blk * 64; }
    else { W = Wl; As = asl; Ad = adl; n0 = NpPad + (blk - nbP) * 64; }

    int wid = t >> 5;
    int lane = t & 31;
    int warp_m = wid >> 1;
    int warp_n = wid & 1;
    int quad = lane >> 2;
    int lane4 = lane & 3;

    float acc[8][4];
    #pragma unroll
    for (int i = 0; i < 8; i++)
        #pragma unroll
        for (int j = 0; j < 4; j++) acc[i][j] = 0.f;

    for (int kk = 0; kk < 128; kk += 32) {
        for (int i = t; i < 1024; i += 256) {
            int j = i >> 3, kq = (i & 7) * 4;
            float4 wv = *(const float4*)&W[j * 128 + kk + kq];
            uint4 cv = make_uint4(to_tf32(wv.x), to_tf32(wv.y), to_tf32(wv.z), to_tf32(wv.w));
            *(uint4*)&sW[j][kq] = cv;
        }
        for (int i = t; i < 512; i += 256) {
            int m = i >> 3, kq = (i & 7) * 4;
            float4 hv = *(const float4*)&h[(n0 + m) * 128 + kk + kq];
            uint4 cv = make_uint4(to_tf32(hv.x), to_tf32(hv.y), to_tf32(hv.z), to_tf32(hv.w));
            *(uint4*)&sH[m][kq] = cv;
        }
        __syncthreads();
        #pragma unroll
        for (int ks = 0; ks < 4; ks++) {
            int kc = ks * 8 + lane4;
            int row = warp_m * 16 + quad;
            unsigned a0 = sH[row][kc];
            unsigned a1 = sH[row + 8][kc];
            unsigned a2 = sH[row][kc + 4];
            unsigned a3 = sH[row + 8][kc + 4];
            #pragma unroll
            for (int nt = 0; nt < 8; nt++) {
                int ncol = warp_n * 64 + nt * 8 + quad;
                unsigned b0 = sW[ncol][kc];
                unsigned b1 = sW[ncol][kc + 4];
                asm volatile(
                    "mma.sync.aligned.m16n8k8.row.col.f32.tf32.tf32.f32 "
                    "{%0,%1,%2,%3}, {%4,%5,%6,%7}, {%8,%9}, {%0,%1,%2,%3};"
                    : "+f"(acc[nt][0]), "+f"(acc[nt][1]), "+f"(acc[nt][2]), "+f"(acc[nt][3])
                    : "r"(a0), "r"(a1), "r"(a2), "r"(a3), "r"(b0), "r"(b1));
            }
        }
        __syncthreads();
    }

    int r0g = n0 + warp_m * 16 + quad;
    int r1g = r0g + 8;
    int cbase = warp_n * 64;
    float ps0h0 = 0.f, ps0h1 = 0.f, ps1h0 = 0.f, ps1h1 = 0.f;
    float pd0h0 = 0.f, pd0h1 = 0.f, pd1h0 = 0.f, pd1h1 = 0.f;
    #pragma unroll
    for (int nt = 0; nt < 8; nt++) {
        int col = cbase + nt * 8 + lane4 * 2;
        float2 as2 = *(const float2*)&As[col];
        float2 ad2 = *(const float2*)&Ad[col];
        *(__half2*)&xph[(size_t)r0g * 128 + col] = __floats2half2_rn(acc[nt][0], acc[nt][1]);
        *(__half2*)&xph[(size_t)r1g * 128 + col] = __floats2half2_rn(acc[nt][2], acc[nt][3]);
        float p0 = acc[nt][0] * as2.x + acc[nt][1] * as2.y;
        float p1 = acc[nt][2] * as2.x + acc[nt][3] * as2.y;
        float q0 = acc[nt][0] * ad2.x + acc[nt][1] * ad2.y;
        float q1 = acc[nt][2] * ad2.x + acc[nt][3] * ad2.y;
        if (nt < 4) { ps0h0 += p0; ps1h0 += p1; pd0h0 += q0; pd1h0 += q1; }
        else        { ps0h1 += p0; ps1h1 += p1; pd0h1 += q0; pd1h1 += q1; }
    }
    #pragma unroll
    for (int off = 1; off <= 2; off <<= 1) {
        ps0h0 += __shfl_xor_sync(0xffffffff, ps0h0, off);
        ps0h1 += __shfl_xor_sync(0xffffffff, ps0h1, off);
        ps1h0 += __shfl_xor_sync(0xffffffff, ps1h0, off);
        ps1h1 += __shfl_xor_sync(0xffffffff, ps1h1, off);
        pd0h0 += __shfl_xor_sync(0xffffffff, pd0h0, off);
        pd0h1 += __shfl_xor_sync(0xffffffff, pd0h1, off);
        pd1h0 += __shfl_xor_sync(0xffffffff, pd1h0, off);
        pd1h1 += __shfl_xor_sync(0xffffffff, pd1h1, off);
    }
    if (lane4 == 0) {
        int h0 = warp_n * 2, h1 = h0 + 1;
        asn[r0g * 4 + h0] = ps0h0; asn[r0g * 4 + h1] = ps0h1;
        asn[r1g * 4 + h0] = ps1h0; asn[r1g * 4 + h1] = ps1h1;
        adn[r0g * 4 + h0] = pd0h0; adn[r0g * 4 + h1] = pd0h1;
        adn[r1g * 4 + h0] = pd1h0; adn[r1g * 4 + h1] = pd1h1;
    }
}

// ---------------- aggregation: no-max softmax, fp16 gather, 4-way unroll --------
// Fully associative (no running max), so edges batch freely: 4 csr/xp/asn loads
// issued back-to-back per block, no rolling-pipeline register rotation.
__global__ void k_aggr(const __half* __restrict__ xph, const float* __restrict__ asn,
                       const float* __restrict__ adn,
                       const float* __restrict__ biasP, const float* __restrict__ biasL,
                       const int* __restrict__ indptr, const int* __restrict__ cnt,
                       const int* __restrict__ csr,
                       float* __restrict__ hout, int Np, int NpPad, int Nl) {
    int n = (blockIdx.x * blockDim.x + threadIdx.x) >> 5;
    int lane = threadIdx.x & 31;
    const float* bias;
    if (n < NpPad) { if (n >= Np) return; bias = biasP; }
    else { if (n - NpPad >= Nl) return; bias = biasL; }
    int hd = lane >> 3;
    int j = lane * 4;
    int base = indptr[n];
    int deg = cnt[n];
    float adn_n = adn[n * 4 + hd];
    float denom = 0.f;
    float4 acc = make_float4(0.f, 0.f, 0.f, 0.f);

    int i = 0;
    for (; i + 4 <= deg; i += 4) {
        int s0 = csr[base + i];
        int s1 = csr[base + i + 1];
        int s2 = csr[base + i + 2];
        int s3 = csr[base + i + 3];
        uint2 x0 = *(const uint2*)(xph + (size_t)s0 * 128 + j);
        uint2 x1 = *(const uint2*)(xph + (size_t)s1 * 128 + j);
        uint2 x2 = *(const uint2*)(xph + (size_t)s2 * 128 + j);
        uint2 x3 = *(const uint2*)(xph + (size_t)s3 * 128 + j);
        float a0 = asn[s0 * 4 + hd];
        float a1 = asn[s1 * 4 + hd];
        float a2 = asn[s2 * 4 + hd];
        float a3 = asn[s3 * 4 + hd];
        float e0 = a0 + adn_n; e0 = (e0 >= 0.f) ? e0 : 0.2f * e0;
        float e1 = a1 + adn_n; e1 = (e1 >= 0.f) ? e1 : 0.2f * e1;
        float e2 = a2 + adn_n; e2 = (e2 >= 0.f) ? e2 : 0.2f * e2;
        float e3 = a3 + adn_n; e3 = (e3 >= 0.f) ? e3 : 0.2f * e3;
        float w0 = __expf(fminf(e0, 60.f));
        float w1 = __expf(fminf(e1, 60.f));
        float w2 = __expf(fminf(e2, 60.f));
        float w3 = __expf(fminf(e3, 60.f));
        denom += (w0 + w1) + (w2 + w3);
        float2 l0 = __half22float2(*(__half2*)&x0.x), h0 = __half22float2(*(__half2*)&x0.y);
        float2 l1 = __half22float2(*(__half2*)&x1.x), h1 = __half22float2(*(__half2*)&x1.y);
        float2 l2 = __half22float2(*(__half2*)&x2.x), h2 = __half22float2(*(__half2*)&x2.y);
        float2 l3 = __half22float2(*(__half2*)&x3.x), h3 = __half22float2(*(__half2*)&x3.y);
        acc.x += w0 * l0.x; acc.y += w0 * l0.y; acc.z += w0 * h0.x; acc.w += w0 * h0.y;
        acc.x += w1 * l1.x; acc.y += w1 * l1.y; acc.z += w1 * h1.x; acc.w += w1 * h1.y;
        acc.x += w2 * l2.x; acc.y += w2 * l2.y; acc.z += w2 * h2.x; acc.w += w2 * h2.y;
        acc.x += w3 * l3.x; acc.y += w3 * l3.y; acc.z += w3 * h3.x; acc.w += w3 * h3.y;
    }
    for (; i < deg; i++) {
        int s0 = csr[base + i];
        uint2 x0 = *(const uint2*)(xph + (size_t)s0 * 128 + j);
        float a0 = asn[s0 * 4 + hd];
        float e0 = a0 + adn_n; e0 = (e0 >= 0.f) ? e0 : 0.2f * e0;
        float w0 = __expf(fminf(e0, 60.f));
        float2 l0 = __half22float2(*(__half2*)&x0.x), h0 = __half22float2(*(__half2*)&x0.y);
        denom += w0;
        acc.x += w0 * l0.x; acc.y += w0 * l0.y; acc.z += w0 * h0.x; acc.w += w0 * h0.y;
    }

    float inv = 1.f / (denom + 1e-16f);
    float4 o;
    o.x = fmaxf(acc.x * inv + bias[j + 0], 0.f);
    o.y = fmaxf(acc.y * inv + bias[j + 1], 0.f);
    o.z = fmaxf(acc.z * inv + bias[j + 2], 0.f);
    o.w = fmaxf(acc.w * inv + bias[j + 3], 0.f);
    *(float4*)&hout[n * 128 + j] = o;
}

// ---------------- pooling ----------------
__global__ void k_pool(const float* __restrict__ h, const int* __restrict__ pb,
                       const int* __restrict__ lb, float* pool, int* gc,
                       int Np, int NpPad, int Nl) {
    int j = threadIdx.x;  // 128
    int n0 = blockIdx.x * 64;
    int nend = n0 + 64;
    int curg = -1;
    float acc = 0.f;
    int cacc = 0;
    for (int n = n0; n < nend; n++) {
        int g;
        if (n < Np) g = pb[n];
        else if (n >= NpPad && (n - NpPad) < Nl) g = G + lb[n - NpPad];
        else continue;
        if (g != curg) {
            if (curg >= 0) {
                atomicAdd(&pool[curg * HID + j], acc);
                if (j == 0) atomicAdd(&gc[curg], cacc);
            }
            curg = g; acc = 0.f; cacc = 0;
        }
        acc += h[n * HID + j];
        cacc++;
    }
    if (curg >= 0) {
        atomicAdd(&pool[curg * HID + j], acc);
        if (j == 0) atomicAdd(&gc[curg], cacc);
    }
}

// ---------------- prediction MLP: layers 1+2 fused per group ----------------
__global__ void k_mlp12(const float* __restrict__ pool, const int* __restrict__ gc,
                        const float* __restrict__ w1, const float* __restrict__ b1,
                        const float* __restrict__ w2, const float* __restrict__ b2,
                        float* __restrict__ out2) {
    int g = blockIdx.x, o = threadIdx.x;  // 256 threads
    __shared__ float jv[256];
    __shared__ float h1[256];
    if (o < 128) {
        float c = fmaxf((float)gc[g], 1.f);
        jv[o] = pool[g * HID + o] / c;
    } else {
        float c = fmaxf((float)gc[G + g], 1.f);
        jv[o] = pool[(G + g) * HID + (o - 128)] / c;
    }
    __syncthreads();
    float s = b1[o];
    #pragma unroll 8
    for (int c2 = 0; c2 < 256; c2++) s += jv[c2] * w1[o * 256 + c2];
    h1[o] = fmaxf(s, 0.f);
    __syncthreads();
    if (o < 128) {
        float s2 = b2[o];
        #pragma unroll 8
        for (int c2 = 0; c2 < 256; c2++) s2 += h1[c2] * w2[o * 256 + c2];
        out2[g * 128 + o] = fmaxf(s2, 0.f);
    }
}
__global__ void k_mlp3(const float* __restrict__ in, const float* __restrict__ w,
                       const float* __restrict__ b, float* __restrict__ out) {
    int g = threadIdx.x;
    if (g < G) {
        float s = b[0];
        #pragma unroll 8
        for (int c = 0; c < 128; c++) s += in[g * 128 + c] * w[c];
        out[g] = s;
    }
}

// ---------------- launch ----------------
extern "C" void kernel_launch(void* const* d_in, const int* in_sizes, int n_in,
                              void* d_out, int out_size) {
    const float* px  = (const float*)d_in[0];
    const int*   pei = (const int*)d_in[1];
    const int*   pb  = (const int*)d_in[2];
    const float* lx  = (const float*)d_in[3];
    const int*   lei = (const int*)d_in[4];
    const int*   lb  = (const int*)d_in[5];
    const float* tw1 = (const float*)d_in[6];
    const float* tb1 = (const float*)d_in[7];
    const float* tw2 = (const float*)d_in[8];
    const float* tb2 = (const float*)d_in[9];
    const float* pew = (const float*)d_in[10];
    const float* peb = (const float*)d_in[11];
    const float* lew = (const float*)d_in[12];
    const float* leb = (const float*)d_in[13];
    const float* pgW = (const float*)d_in[14];
    const float* pgs = (const float*)d_in[15];
    const float* pgd = (const float*)d_in[16];
    const float* pgb = (const float*)d_in[17];
    const float* lgW = (const float*)d_in[18];
    const float* lgs = (const float*)d_in[19];
    const float* lgd = (const float*)d_in[20];
    const float* lgb = (const float*)d_in[21];
    const float* prw1 = (const float*)d_in[22];
    const float* prb1 = (const float*)d_in[23];
    const float* prw2 = (const float*)d_in[24];
    const float* prb2 = (const float*)d_in[25];
    const float* prw3 = (const float*)d_in[26];
    const float* prb3 = (const float*)d_in[27];

    int Np = in_sizes[0] / 16, Ep = in_sizes[1] / 2;
    int Nl = in_sizes[3] / 16, El = in_sizes[4] / 2;
    int NpPad = (Np + 63) / 64 * 64;
    int NT = NpPad + (Nl + 63) / 64 * 64;
    int Etot = Ep + El;

    float *h0, *h1, *asn, *adn, *temb, *pool, *m2;
    __half *xph;
    int *cnt, *cur, *indptr, *csr, *gc, *total;
    cudaGetSymbolAddress((void**)&h0, g_h0);
    cudaGetSymbolAddress((void**)&h1, g_h1);
    cudaGetSymbolAddress((void**)&xph, g_xph);
    cudaGetSymbolAddress((void**)&asn, g_asn);
    cudaGetSymbolAddress((void**)&adn, g_adn);
    cudaGetSymbolAddress((void**)&temb, g_temb);
    cudaGetSymbolAddress((void**)&pool, g_pool);
    cudaGetSymbolAddress((void**)&m2, g_m2);
    cudaGetSymbolAddress((void**)&cnt, g_cnt);
    cudaGetSymbolAddress((void**)&cur, g_cur);
    cudaGetSymbolAddress((void**)&indptr, g_indptr);
    cudaGetSymbolAddress((void**)&csr, g_csr);
    cudaGetSymbolAddress((void**)&gc, g_gcnt);
    cudaGetSymbolAddress((void**)&total, g_total);

    const int* pdst = pei + Ep;
    const int* ldst = lei + El;

    int setup_work = NT > 2 * G * HID ? NT : 2 * G * HID;
    k_setup<<<1 + (setup_work + 255) / 256, 256>>>(tw1, tb1, tw2, tb2, temb,
                                                   cnt, cur, pool, gc, total,
                                                   Np, NpPad, Nl, NT);
    k_count<<<(Etot + 255) / 256, 256>>>(pdst, ldst, cnt, Ep, El, NpPad);
    k_alloc<<<(NT + 255) / 256, 256>>>(cnt, indptr, csr, total, Np, NpPad, Nl, NT);
    k_fill<<<(Etot + 255) / 256, 256>>>(pei, pdst, lei, ldst, indptr, cur, csr,
                                        Ep, El, NpPad);
    int nbP32 = NpPad / 32, nbL32 = (Nl + 31) / 32;
    k_encode<<<nbP32 + nbL32, 256>>>(px, lx, pew, peb, lew, leb, temb, h0,
                                     Np, NpPad, Nl, nbP32);

    int nbP64 = NpPad / 64, nbL64 = (Nl + 63) / 64;
    int nAggr = NpPad + Nl;
    int aggrBlocks = (nAggr * 32 + 255) / 256;
    float* hin = h0;
    float* hout = h1;
    for (int l = 0; l < DEPTH; l++) {
        k_gemm_attn<<<nbP64 + nbL64, 256>>>(hin,
            pgW + l * HID * HID, lgW + l * HID * HID,
            pgs + l * HID, pgd + l * HID, lgs + l * HID, lgd + l * HID,
            xph, asn, adn, NpPad, nbP64);
        k_aggr<<<aggrBlocks, 256>>>(xph, asn, adn, pgb + l * HID, lgb + l * HID,
                                    indptr, cnt, csr, hout, Np, NpPad, Nl);
        float* tmp = hin; hin = hout; hout = tmp;
    }

    k_pool<<<(NT + 63) / 64, 128>>>(hin, pb, lb, pool, gc, Np, NpPad, Nl);

    k_mlp12<<<G, 256>>>(pool, gc, prw1, prb1, prw2, prb2, m2);
    k_mlp3<<<1, 32>>>(m2, prw3, prb3, (float*)d_out);
}